// round 1
// baseline (speedup 1.0000x reference)
#include <cuda_runtime.h>
#include <math.h>

// Problem constants
#define B_TOT   4096
#define NSEQ    64
#define CDIM    192
#define NH      6
#define HD      32
#define NW      64
#define CPBH    512
#define NTHREADS 384

// Shared memory layout (floats)
//  sx   : 64*193   = 12352   (x window, padded; reused as attn-out buffer)
//  sq   : 6*64*33  = 12672   (q, padded stride 33 -> conflict-free row reads)
//  sk   : 6*64*32  = 12288   (k, stride 32 -> float4 broadcast)
//  sv   : 6*64*32  = 12288
//  sw   : 192*17   =  3264   (weight staging tile)
//  sinvq: 384, sinvk: 384, sscale: 8
#define SX_OFF    0
#define SQ_OFF    (SX_OFF + 64*193)
#define SK_OFF    (SQ_OFF + NH*64*33)
#define SV_OFF    (SK_OFF + NH*64*32)
#define SW_OFF    (SV_OFF + NH*64*32)
#define SIQ_OFF   (SW_OFF + 192*17)
#define SIK_OFF   (SIQ_OFF + 384)
#define SSC_OFF   (SIK_OFF + 384)
#define SMEM_FLOATS (SSC_OFF + 8)
#define SMEM_BYTES (SMEM_FLOATS * 4)

// CPB bias table: 16*sigmoid(rpb) laid out [h][i][j]
__device__ float g_bias[NH * NSEQ * NSEQ];

// ---------------------------------------------------------------------------
// Kernel 1: continuous relative position bias (tiny MLP), one block.
// ---------------------------------------------------------------------------
__global__ void cpb_kernel(const float* __restrict__ w1,
                           const float* __restrict__ b1,
                           const float* __restrict__ w2)
{
    __shared__ float rpb[225 * NH];
    const int t = threadIdx.x;           // 256 threads
    const float inv_log2_8 = 1.0f / 3.0f;

    for (int e = t; e < 225 * NH; e += 256) {
        int te = e / NH, h = e % NH;
        int i = te / 15, j = te % 15;
        float cy = (float)(i - 7) * (8.0f / 7.0f);
        float cx = (float)(j - 7) * (8.0f / 7.0f);
        cy = copysignf(log2f(fabsf(cy) + 1.0f), cy) * inv_log2_8;
        cx = copysignf(log2f(fabsf(cx) + 1.0f), cx) * inv_log2_8;
        float acc = 0.0f;
        for (int k = 0; k < CPBH; k++) {
            float hm = cy * w1[2 * k] + cx * w1[2 * k + 1] + b1[k];
            hm = fmaxf(hm, 0.0f);
            acc += hm * w2[h * CPBH + k];
        }
        rpb[te * NH + h] = acc;
    }
    __syncthreads();

    for (int e = t; e < NH * NSEQ * NSEQ; e += 256) {
        int h = e / (NSEQ * NSEQ);
        int rr = e % (NSEQ * NSEQ);
        int i = rr / NSEQ, j = rr % NSEQ;
        int dy = (i >> 3) - (j >> 3) + 7;
        int dx = (i & 7) - (j & 7) + 7;
        float v = rpb[(dy * 15 + dx) * NH + h];
        g_bias[e] = 16.0f / (1.0f + expf(-v));
    }
}

// ---------------------------------------------------------------------------
// Kernel 2: fully fused window attention. One block per window.
// ---------------------------------------------------------------------------
__global__ __launch_bounds__(NTHREADS)
void win_attn_kernel(const float* __restrict__ x,
                     const float* __restrict__ mask,
                     const float* __restrict__ qkv_w,
                     const float* __restrict__ q_bias,
                     const float* __restrict__ v_bias,
                     const float* __restrict__ logit_scale,
                     const float* __restrict__ proj_w,
                     const float* __restrict__ proj_b,
                     float* __restrict__ out)
{
    extern __shared__ float sm[];
    float* sx     = sm + SX_OFF;
    float* sq     = sm + SQ_OFF;
    float* sk     = sm + SK_OFF;
    float* sv     = sm + SV_OFF;
    float* sw     = sm + SW_OFF;
    float* sinvq  = sm + SIQ_OFF;
    float* sinvk  = sm + SIK_OFF;
    float* sscale = sm + SSC_OFF;

    const int t = threadIdx.x;
    const int b = blockIdx.x;
    const int widx = b & (NW - 1);
    const float* xb = x + (size_t)b * NSEQ * CDIM;

    // -------- load x window into smem (padded stride 193) --------
    for (int idx = t; idx < NSEQ * CDIM / 4; idx += NTHREADS) {
        float4 v4 = ((const float4*)xb)[idx];
        int n = (idx * 4) / CDIM;
        int k = (idx * 4) % CDIM;
        float* d = &sx[n * 193 + k];
        d[0] = v4.x; d[1] = v4.y; d[2] = v4.z; d[3] = v4.w;
    }
    if (t < NH) sscale[t] = __expf(fminf(logit_scale[t], 4.60517019f)); // ln(100)
    __syncthreads();

    // -------- Phase 1: QKV GEMM  (64 x 576 x 192) --------
    {
        const int ty = t / 24;    // 0..15 (row group, 4 rows each)
        const int tx = t % 24;    // 0..23 (6 output channels each)
        const int r0 = ty * 4;

        for (int cb = 0; cb < 576; cb += 144) {
            float acc[4][6];
            #pragma unroll
            for (int i = 0; i < 4; i++)
                #pragma unroll
                for (int j = 0; j < 6; j++) acc[i][j] = 0.0f;

            for (int kt = 0; kt < CDIM; kt += 16) {
                // stage weight tile [144][16] -> sw (padded 17)
                #pragma unroll
                for (int u = 0; u < 6; u++) {
                    int idx = t + u * NTHREADS;        // < 2304
                    int cc = idx >> 4, kk = idx & 15;
                    sw[cc * 17 + kk] = qkv_w[(cb + cc) * CDIM + kt + kk];
                }
                __syncthreads();
                #pragma unroll
                for (int kk = 0; kk < 16; kk++) {
                    float ax[4], wb[6];
                    #pragma unroll
                    for (int i = 0; i < 4; i++) ax[i] = sx[(r0 + i) * 193 + kt + kk];
                    #pragma unroll
                    for (int j = 0; j < 6; j++) wb[j] = sw[(tx * 6 + j) * 17 + kk];
                    #pragma unroll
                    for (int i = 0; i < 4; i++)
                        #pragma unroll
                        for (int j = 0; j < 6; j++)
                            acc[i][j] += ax[i] * wb[j];
                }
                __syncthreads();
            }
            // scatter to sq / sk / sv with biases
            #pragma unroll
            for (int i = 0; i < 4; i++) {
                int n = r0 + i;
                #pragma unroll
                for (int j = 0; j < 6; j++) {
                    int c = cb + tx * 6 + j;
                    int s = c / 192;
                    int rem = c - s * 192;
                    int h = rem >> 5, d = rem & 31;
                    float val = acc[i][j];
                    if (s == 0)      { val += q_bias[rem]; sq[(h * 64 + n) * 33 + d] = val; }
                    else if (s == 1) { sk[(h * 64 + n) * 32 + d] = val; }
                    else             { val += v_bias[rem]; sv[(h * 64 + n) * 32 + d] = val; }
                }
            }
        }
    }
    __syncthreads();

    // -------- Phase 1b: per-row inverse norms of q and k --------
    {
        int w = t >> 5, lane = t & 31;
        for (int task = w; task < 24; task += 12) {
            int typ   = task / 12;            // 0 = q, 1 = k
            int hh    = (task % 12) >> 1;
            int rbase = (task & 1) * 32;
            for (int r = 0; r < 32; r++) {
                int row = hh * 64 + rbase + r;
                float vq = typ ? sk[row * 32 + lane] : sq[row * 33 + lane];
                float ss = vq * vq;
                #pragma unroll
                for (int off = 16; off; off >>= 1)
                    ss += __shfl_xor_sync(0xffffffffu, ss, off);
                if (lane == 0) {
                    float inv = 1.0f / fmaxf(sqrtf(ss), 1e-12f);
                    if (typ) sinvk[row] = inv; else sinvq[row] = inv;
                }
            }
        }
    }
    __syncthreads();

    // -------- Phase 2: per-warp per-head attention, S row in registers --------
    {
        int w = t >> 5, lane = t & 31;
        int h = w >> 1;
        int r = (w & 1) * 32 + lane;
        int row = h * 64 + r;

        float qv[32];
        float qs = sinvq[row] * sscale[h];
        #pragma unroll
        for (int d = 0; d < 32; d++) qv[d] = sq[row * 33 + d] * qs;

        float S[64];
        const float* biasrow = &g_bias[(h * 64 + r) * 64];
        const float* maskrow = &mask[((size_t)widx * 64 + r) * 64];

        #pragma unroll
        for (int m = 0; m < 64; m++) {
            const float4* kp = (const float4*)&sk[(h * 64 + m) * 32];
            float dot = 0.0f;
            #pragma unroll
            for (int q4 = 0; q4 < 8; q4++) {
                float4 kk = kp[q4];
                dot += qv[q4 * 4 + 0] * kk.x + qv[q4 * 4 + 1] * kk.y
                     + qv[q4 * 4 + 2] * kk.z + qv[q4 * 4 + 3] * kk.w;
            }
            S[m] = dot * sinvk[h * 64 + m] + biasrow[m] + maskrow[m];
        }

        float mx = -1e30f;
        #pragma unroll
        for (int m = 0; m < 64; m++) mx = fmaxf(mx, S[m]);
        float sum = 0.0f;
        #pragma unroll
        for (int m = 0; m < 64; m++) { S[m] = __expf(S[m] - mx); sum += S[m]; }
        float rs = 1.0f / sum;

        float o[32];
        #pragma unroll
        for (int d = 0; d < 32; d++) o[d] = 0.0f;
        #pragma unroll
        for (int m = 0; m < 64; m++) {
            float p = S[m];
            const float4* vp = (const float4*)&sv[(h * 64 + m) * 32];
            #pragma unroll
            for (int q4 = 0; q4 < 8; q4++) {
                float4 vv = vp[q4];
                o[q4 * 4 + 0] += p * vv.x; o[q4 * 4 + 1] += p * vv.y;
                o[q4 * 4 + 2] += p * vv.z; o[q4 * 4 + 3] += p * vv.w;
            }
        }
        // attn output -> sx buffer as [n][h*32+d], stride 193
        #pragma unroll
        for (int d = 0; d < 32; d++)
            sx[r * 193 + h * 32 + d] = o[d] * rs;
    }
    __syncthreads();

    // -------- Phase 3: output projection (64 x 192 x 192) --------
    {
        const int ty = t / 24;   // row group (4 rows)
        const int tx = t % 24;   // col group (8 cols)
        float acc[4][8];
        #pragma unroll
        for (int i = 0; i < 4; i++)
            #pragma unroll
            for (int j = 0; j < 8; j++) acc[i][j] = 0.0f;

        for (int kt = 0; kt < 192; kt += 16) {
            #pragma unroll
            for (int u = 0; u < 8; u++) {
                int idx = t + u * NTHREADS;   // < 3072
                int cc = idx >> 4, kk = idx & 15;
                sw[cc * 17 + kk] = proj_w[cc * 192 + kt + kk];
            }
            __syncthreads();
            #pragma unroll
            for (int kk = 0; kk < 16; kk++) {
                float ax[4], wb[8];
                #pragma unroll
                for (int i = 0; i < 4; i++) ax[i] = sx[(ty * 4 + i) * 193 + kt + kk];
                #pragma unroll
                for (int j = 0; j < 8; j++) wb[j] = sw[(tx * 8 + j) * 17 + kk];
                #pragma unroll
                for (int i = 0; i < 4; i++)
                    #pragma unroll
                    for (int j = 0; j < 8; j++)
                        acc[i][j] += ax[i] * wb[j];
            }
            __syncthreads();
        }

        float* ob = out + (size_t)b * NSEQ * CDIM;
        const int cbase = tx * 8;
        float pb[8];
        #pragma unroll
        for (int j = 0; j < 8; j++) pb[j] = proj_b[cbase + j];
        #pragma unroll
        for (int i = 0; i < 4; i++) {
            int n = ty * 4 + i;
            float4 v0 = make_float4(acc[i][0] + pb[0], acc[i][1] + pb[1],
                                    acc[i][2] + pb[2], acc[i][3] + pb[3]);
            float4 v1 = make_float4(acc[i][4] + pb[4], acc[i][5] + pb[5],
                                    acc[i][6] + pb[6], acc[i][7] + pb[7]);
            ((float4*)&ob[n * 192 + cbase])[0] = v0;
            ((float4*)&ob[n * 192 + cbase])[1] = v1;
        }
    }
}

// ---------------------------------------------------------------------------
extern "C" void kernel_launch(void* const* d_in, const int* in_sizes, int n_in,
                              void* d_out, int out_size)
{
    const float* x           = (const float*)d_in[0];
    const float* mask        = (const float*)d_in[1];
    const float* qkv_w       = (const float*)d_in[2];
    const float* q_bias      = (const float*)d_in[3];
    const float* v_bias      = (const float*)d_in[4];
    const float* logit_scale = (const float*)d_in[5];
    const float* cpb_w1      = (const float*)d_in[6];
    const float* cpb_b1      = (const float*)d_in[7];
    const float* cpb_w2      = (const float*)d_in[8];
    const float* proj_w      = (const float*)d_in[9];
    const float* proj_b      = (const float*)d_in[10];
    float* out = (float*)d_out;

    cudaFuncSetAttribute(win_attn_kernel,
                         cudaFuncAttributeMaxDynamicSharedMemorySize, SMEM_BYTES);

    cpb_kernel<<<1, 256>>>(cpb_w1, cpb_b1, cpb_w2);
    win_attn_kernel<<<B_TOT, NTHREADS, SMEM_BYTES>>>(
        x, mask, qkv_w, q_bias, v_bias, logit_scale, proj_w, proj_b, out);
}

// round 2
// speedup vs baseline: 1.3637x; 1.3637x over previous
#include <cuda_runtime.h>
#include <math.h>
#include <stdint.h>

// Problem constants
#define B_TOT   4096
#define NSEQ    64
#define CDIM    192
#define NH      6
#define NW      64
#define CPBH    512
#define NTHREADS 384

// Shared memory layout (floats)
//  sx : 64 x 196 (stride 196 ≡ 4 mod 32 -> conflict-free mma A loads, float4-aligned)
//  sq : 6*64*33  (aliased: weight staging buffer, stride 20, up to 576*20=11520)
//  sk : 6*64*32
//  sv : 6*64*32
#define SXS     196
#define SX_OFF  0
#define SQ_OFF  (SX_OFF + 64*SXS)         // 12544
#define SK_OFF  (SQ_OFF + NH*64*33)       // +12672
#define SV_OFF  (SK_OFF + NH*64*32)       // +12288
#define SIQ_OFF (SV_OFF + NH*64*32)       // +12288
#define SIK_OFF (SIQ_OFF + 384)
#define SSC_OFF (SIK_OFF + 384)
#define SMEM_FLOATS (SSC_OFF + 8)
#define SMEM_BYTES (SMEM_FLOATS * 4)

__device__ float g_bias[NH * NSEQ * NSEQ];

// ---------------- tf32 helpers ----------------
__device__ __forceinline__ uint32_t f2tf(float f) {
    uint32_t u; asm("cvt.rna.tf32.f32 %0, %1;" : "=r"(u) : "f"(f)); return u;
}
__device__ __forceinline__ void mma8(float* d, const uint32_t* a, uint32_t b0, uint32_t b1) {
    asm volatile("mma.sync.aligned.m16n8k8.row.col.f32.tf32.tf32.f32 "
                 "{%0,%1,%2,%3},{%4,%5,%6,%7},{%8,%9},{%0,%1,%2,%3};"
                 : "+f"(d[0]), "+f"(d[1]), "+f"(d[2]), "+f"(d[3])
                 : "r"(a[0]), "r"(a[1]), "r"(a[2]), "r"(a[3]), "r"(b0), "r"(b1));
}

// ---------------------------------------------------------------------------
// Kernel 1: continuous relative position bias (tiny MLP), one block.
// ---------------------------------------------------------------------------
__global__ void cpb_kernel(const float* __restrict__ w1,
                           const float* __restrict__ b1,
                           const float* __restrict__ w2)
{
    __shared__ float rpb[225 * NH];
    const int t = threadIdx.x;
    const float inv_log2_8 = 1.0f / 3.0f;

    for (int e = t; e < 225 * NH; e += 256) {
        int te = e / NH, h = e % NH;
        int i = te / 15, j = te % 15;
        float cy = (float)(i - 7) * (8.0f / 7.0f);
        float cx = (float)(j - 7) * (8.0f / 7.0f);
        cy = copysignf(log2f(fabsf(cy) + 1.0f), cy) * inv_log2_8;
        cx = copysignf(log2f(fabsf(cx) + 1.0f), cx) * inv_log2_8;
        float acc = 0.0f;
        for (int k = 0; k < CPBH; k++) {
            float hm = cy * w1[2 * k] + cx * w1[2 * k + 1] + b1[k];
            hm = fmaxf(hm, 0.0f);
            acc += hm * w2[h * CPBH + k];
        }
        rpb[te * NH + h] = acc;
    }
    __syncthreads();

    for (int e = t; e < NH * NSEQ * NSEQ; e += 256) {
        int h = e / (NSEQ * NSEQ);
        int rr = e % (NSEQ * NSEQ);
        int i = rr / NSEQ, j = rr % NSEQ;
        int dy = (i >> 3) - (j >> 3) + 7;
        int dx = (i & 7) - (j & 7) + 7;
        float v = rpb[(dy * 15 + dx) * NH + h];
        g_bias[e] = 16.0f / (1.0f + expf(-v));
    }
}

// ---------------------------------------------------------------------------
// Kernel 2: fused window attention, GEMMs on tensor cores (3xTF32 mma.sync)
// ---------------------------------------------------------------------------
__global__ __launch_bounds__(NTHREADS)
void win_attn_kernel(const float* __restrict__ x,
                     const float* __restrict__ mask,
                     const float* __restrict__ qkv_w,
                     const float* __restrict__ q_bias,
                     const float* __restrict__ v_bias,
                     const float* __restrict__ logit_scale,
                     const float* __restrict__ proj_w,
                     const float* __restrict__ proj_b,
                     float* __restrict__ out)
{
    extern __shared__ float sm[];
    float* sx     = sm + SX_OFF;
    float* sq     = sm + SQ_OFF;
    float* sw     = sm + SQ_OFF;     // staging aliases q region
    float* sk     = sm + SK_OFF;
    float* sv     = sm + SV_OFF;
    float* sinvq  = sm + SIQ_OFF;
    float* sinvk  = sm + SIK_OFF;
    float* sscale = sm + SSC_OFF;

    const int t = threadIdx.x;
    const int b = blockIdx.x;
    const int widx = b & (NW - 1);
    const float* xb = x + (size_t)b * NSEQ * CDIM;

    const int w    = t >> 5;
    const int lane = t & 31;
    const int g    = lane >> 2;   // fragment row group 0..7
    const int qd   = lane & 3;    // fragment k/col sub 0..3

    // -------- load x window into smem (stride 196) --------
    for (int idx = t; idx < NSEQ * CDIM / 4; idx += NTHREADS) {
        float4 v4 = ((const float4*)xb)[idx];
        int n = (idx * 4) / CDIM;
        int k = (idx * 4) % CDIM;
        *(float4*)&sx[n * SXS + k] = v4;
    }
    if (t < NH) sscale[t] = __expf(fminf(logit_scale[t], 4.60517019f)); // ln(100)
    __syncthreads();

    // ================= Phase 1: QKV GEMM (64 x 576 x 192), 3xTF32 ==========
    {
        const int mg = w & 1;        // row group: 2 m16 tiles at rows 32*mg
        const int ng = w >> 1;       // 0..5: 96-col group
        const int cb = ng * 96;

        float acc[2][12][4];
        #pragma unroll
        for (int a = 0; a < 2; a++)
            #pragma unroll
            for (int nt = 0; nt < 12; nt++)
                #pragma unroll
                for (int e = 0; e < 4; e++) acc[a][nt][e] = 0.0f;

        for (int kc = 0; kc < 12; kc++) {
            __syncthreads();
            // stage qkv_w[0..575][kc*16 .. +16) -> sw (stride 20)
            #pragma unroll
            for (int u = 0; u < 6; u++) {
                int e = t + u * NTHREADS;       // < 2304 float4 groups
                int c = e >> 2, kq = e & 3;
                float4 wv = *(const float4*)&qkv_w[c * 192 + kc * 16 + kq * 4];
                *(float4*)&sw[c * 20 + kq * 4] = wv;
            }
            __syncthreads();

            #pragma unroll
            for (int kst = 0; kst < 2; kst++) {
                // A fragments (x rows), tf32 hi/lo
                uint32_t ahi[2][4], alo[2][4];
                #pragma unroll
                for (int mt = 0; mt < 2; mt++) {
                    const float* xr = &sx[(mg * 32 + mt * 16 + g) * SXS + kc * 16 + kst * 8 + qd];
                    float v0 = xr[0];            // (row g,   col qd)
                    float v1 = xr[4];            // (row g,   col qd+4)
                    float v2 = xr[8 * SXS];      // (row g+8, col qd)
                    float v3 = xr[8 * SXS + 4];  // (row g+8, col qd+4)
                    ahi[mt][0] = f2tf(v0); alo[mt][0] = f2tf(v0 - __uint_as_float(ahi[mt][0]));
                    ahi[mt][1] = f2tf(v2); alo[mt][1] = f2tf(v2 - __uint_as_float(ahi[mt][1]));
                    ahi[mt][2] = f2tf(v1); alo[mt][2] = f2tf(v1 - __uint_as_float(ahi[mt][2]));
                    ahi[mt][3] = f2tf(v3); alo[mt][3] = f2tf(v3 - __uint_as_float(ahi[mt][3]));
                }
                #pragma unroll
                for (int nt = 0; nt < 12; nt++) {
                    const float* wp = &sw[(cb + nt * 8 + g) * 20 + kst * 8 + qd];
                    float b0f = wp[0];
                    float b1f = wp[4];
                    uint32_t bh0 = f2tf(b0f), bl0 = f2tf(b0f - __uint_as_float(bh0));
                    uint32_t bh1 = f2tf(b1f), bl1 = f2tf(b1f - __uint_as_float(bh1));
                    #pragma unroll
                    for (int mt = 0; mt < 2; mt++) {
                        mma8(acc[mt][nt], ahi[mt], bh0, bh1);
                        mma8(acc[mt][nt], ahi[mt], bl0, bl1);
                        mma8(acc[mt][nt], alo[mt], bh0, bh1);
                    }
                }
            }
        }
        __syncthreads();   // all reads of sw done before writing q (aliased)

        // scatter accumulators to sq / sk / sv (s constant per warp)
        const int s = ng >> 1;   // 0=q, 1=k, 2=v
        #pragma unroll
        for (int mt = 0; mt < 2; mt++) {
            #pragma unroll
            for (int nt = 0; nt < 12; nt++) {
                int col0 = cb + nt * 8 + qd * 2;
                int rem = col0 - s * 192;            // 0..190, even
                int h = rem >> 5, d = rem & 31;
                #pragma unroll
                for (int rr = 0; rr < 2; rr++) {
                    int n = mg * 32 + mt * 16 + g + rr * 8;
                    float v0 = acc[mt][nt][rr * 2 + 0];
                    float v1 = acc[mt][nt][rr * 2 + 1];
                    if (s == 0) {
                        sq[(h * 64 + n) * 33 + d]     = v0 + q_bias[rem];
                        sq[(h * 64 + n) * 33 + d + 1] = v1 + q_bias[rem + 1];
                    } else if (s == 1) {
                        sk[(h * 64 + n) * 32 + d]     = v0;
                        sk[(h * 64 + n) * 32 + d + 1] = v1;
                    } else {
                        sv[(h * 64 + n) * 32 + d]     = v0 + v_bias[rem];
                        sv[(h * 64 + n) * 32 + d + 1] = v1 + v_bias[rem + 1];
                    }
                }
            }
        }
    }
    __syncthreads();

    // -------- Phase 1b: per-row inverse norms of q and k --------
    {
        for (int task = w; task < 24; task += 12) {
            int typ   = task / 12;
            int hh    = (task % 12) >> 1;
            int rbase = (task & 1) * 32;
            for (int r = 0; r < 32; r++) {
                int row = hh * 64 + rbase + r;
                float vq = typ ? sk[row * 32 + lane] : sq[row * 33 + lane];
                float ss = vq * vq;
                #pragma unroll
                for (int off = 16; off; off >>= 1)
                    ss += __shfl_xor_sync(0xffffffffu, ss, off);
                if (lane == 0) {
                    float inv = 1.0f / fmaxf(sqrtf(ss), 1e-12f);
                    if (typ) sinvk[row] = inv; else sinvq[row] = inv;
                }
            }
        }
    }
    __syncthreads();

    // -------- Phase 2: per-warp per-head attention, S row in registers --------
    {
        int h = w >> 1;
        int r = (w & 1) * 32 + lane;
        int row = h * 64 + r;

        float qv[32];
        float qs = sinvq[row] * sscale[h];
        #pragma unroll
        for (int d = 0; d < 32; d++) qv[d] = sq[row * 33 + d] * qs;

        float S[64];
        const float* biasrow = &g_bias[(h * 64 + r) * 64];
        const float* maskrow = &mask[((size_t)widx * 64 + r) * 64];

        #pragma unroll
        for (int m = 0; m < 64; m++) {
            const float4* kp = (const float4*)&sv[-NH*64*32 + (h * 64 + m) * 32]; // sk
            kp = (const float4*)&sm[SK_OFF + (h * 64 + m) * 32];
            float dot = 0.0f;
            #pragma unroll
            for (int q4 = 0; q4 < 8; q4++) {
                float4 kk = kp[q4];
                dot += qv[q4 * 4 + 0] * kk.x + qv[q4 * 4 + 1] * kk.y
                     + qv[q4 * 4 + 2] * kk.z + qv[q4 * 4 + 3] * kk.w;
            }
            S[m] = dot * sinvk[h * 64 + m] + biasrow[m] + maskrow[m];
        }

        float mx = -1e30f;
        #pragma unroll
        for (int m = 0; m < 64; m++) mx = fmaxf(mx, S[m]);
        float sum = 0.0f;
        #pragma unroll
        for (int m = 0; m < 64; m++) { S[m] = __expf(S[m] - mx); sum += S[m]; }
        float rs = 1.0f / sum;

        float o[32];
        #pragma unroll
        for (int d = 0; d < 32; d++) o[d] = 0.0f;
        #pragma unroll
        for (int m = 0; m < 64; m++) {
            float p = S[m];
            const float4* vp = (const float4*)&sv[(h * 64 + m) * 32];
            #pragma unroll
            for (int q4 = 0; q4 < 8; q4++) {
                float4 vv = vp[q4];
                o[q4 * 4 + 0] += p * vv.x; o[q4 * 4 + 1] += p * vv.y;
                o[q4 * 4 + 2] += p * vv.z; o[q4 * 4 + 3] += p * vv.w;
            }
        }
        #pragma unroll
        for (int d = 0; d < 32; d++)
            sx[r * SXS + h * 32 + d] = o[d] * rs;
    }
    __syncthreads();

    // ================= Phase 3: proj GEMM (64 x 192 x 192), 3xTF32 ==========
    {
        const int mg = w & 1;
        const int ng = w >> 1;       // 0..5: 32-col group
        const int cb = ng * 32;

        float acc[2][4][4];
        #pragma unroll
        for (int a = 0; a < 2; a++)
            #pragma unroll
            for (int nt = 0; nt < 4; nt++)
                #pragma unroll
                for (int e = 0; e < 4; e++) acc[a][nt][e] = 0.0f;

        for (int kc = 0; kc < 12; kc++) {
            __syncthreads();
            #pragma unroll
            for (int u = 0; u < 2; u++) {
                int e = t + u * NTHREADS;       // < 768 float4 groups
                int c = e >> 2, kq = e & 3;
                float4 wv = *(const float4*)&proj_w[c * 192 + kc * 16 + kq * 4];
                *(float4*)&sw[c * 20 + kq * 4] = wv;
            }
            __syncthreads();

            #pragma unroll
            for (int kst = 0; kst < 2; kst++) {
                uint32_t ahi[2][4], alo[2][4];
                #pragma unroll
                for (int mt = 0; mt < 2; mt++) {
                    const float* xr = &sx[(mg * 32 + mt * 16 + g) * SXS + kc * 16 + kst * 8 + qd];
                    float v0 = xr[0];
                    float v1 = xr[4];
                    float v2 = xr[8 * SXS];
                    float v3 = xr[8 * SXS + 4];
                    ahi[mt][0] = f2tf(v0); alo[mt][0] = f2tf(v0 - __uint_as_float(ahi[mt][0]));
                    ahi[mt][1] = f2tf(v2); alo[mt][1] = f2tf(v2 - __uint_as_float(ahi[mt][1]));
                    ahi[mt][2] = f2tf(v1); alo[mt][2] = f2tf(v1 - __uint_as_float(ahi[mt][2]));
                    ahi[mt][3] = f2tf(v3); alo[mt][3] = f2tf(v3 - __uint_as_float(ahi[mt][3]));
                }
                #pragma unroll
                for (int nt = 0; nt < 4; nt++) {
                    const float* wp = &sw[(cb + nt * 8 + g) * 20 + kst * 8 + qd];
                    float b0f = wp[0];
                    float b1f = wp[4];
                    uint32_t bh0 = f2tf(b0f), bl0 = f2tf(b0f - __uint_as_float(bh0));
                    uint32_t bh1 = f2tf(b1f), bl1 = f2tf(b1f - __uint_as_float(bh1));
                    #pragma unroll
                    for (int mt = 0; mt < 2; mt++) {
                        mma8(acc[mt][nt], ahi[mt], bh0, bh1);
                        mma8(acc[mt][nt], ahi[mt], bl0, bl1);
                        mma8(acc[mt][nt], alo[mt], bh0, bh1);
                    }
                }
            }
        }

        float* ob = out + (size_t)b * NSEQ * CDIM;
        #pragma unroll
        for (int mt = 0; mt < 2; mt++) {
            #pragma unroll
            for (int nt = 0; nt < 4; nt++) {
                int col0 = cb + nt * 8 + qd * 2;
                float pb0 = proj_b[col0], pb1 = proj_b[col0 + 1];
                #pragma unroll
                for (int rr = 0; rr < 2; rr++) {
                    int n = mg * 32 + mt * 16 + g + rr * 8;
                    float2 o2 = make_float2(acc[mt][nt][rr * 2 + 0] + pb0,
                                            acc[mt][nt][rr * 2 + 1] + pb1);
                    *(float2*)&ob[n * 192 + col0] = o2;
                }
            }
        }
    }
}

// ---------------------------------------------------------------------------
extern "C" void kernel_launch(void* const* d_in, const int* in_sizes, int n_in,
                              void* d_out, int out_size)
{
    const float* x           = (const float*)d_in[0];
    const float* mask        = (const float*)d_in[1];
    const float* qkv_w       = (const float*)d_in[2];
    const float* q_bias      = (const float*)d_in[3];
    const float* v_bias      = (const float*)d_in[4];
    const float* logit_scale = (const float*)d_in[5];
    const float* cpb_w1      = (const float*)d_in[6];
    const float* cpb_b1      = (const float*)d_in[7];
    const float* cpb_w2      = (const float*)d_in[8];
    const float* proj_w      = (const float*)d_in[9];
    const float* proj_b      = (const float*)d_in[10];
    float* out = (float*)d_out;

    cudaFuncSetAttribute(win_attn_kernel,
                         cudaFuncAttributeMaxDynamicSharedMemorySize, SMEM_BYTES);

    cpb_kernel<<<1, 256>>>(cpb_w1, cpb_b1, cpb_w2);
    win_attn_kernel<<<B_TOT, NTHREADS, SMEM_BYTES>>>(
        x, mask, qkv_w, q_bias, v_bias, logit_scale, proj_w, proj_b, out);
}

// round 3
// speedup vs baseline: 1.5931x; 1.1683x over previous
#include <cuda_runtime.h>
#include <math.h>
#include <stdint.h>

// Problem constants
#define B_TOT   4096
#define NSEQ    64
#define CDIM    192
#define NH      6
#define NW      64
#define CPBH    512
#define NTHREADS 384

// Shared memory layout (floats)
#define SXS     196
#define SX_OFF  0
#define SQ_OFF  (SX_OFF + 64*SXS)
#define SK_OFF  (SQ_OFF + NH*64*33)
#define SV_OFF  (SK_OFF + NH*64*32)
#define SIQ_OFF (SV_OFF + NH*64*32)
#define SIK_OFF (SIQ_OFF + 384)
#define SSC_OFF (SIK_OFF + 384)
#define SMEM_FLOATS (SSC_OFF + 8)
#define SMEM_BYTES (SMEM_FLOATS * 4)

__device__ float g_bias[NH * NSEQ * NSEQ];

// Precomputed fragment-ordered tf32 hi/lo weight tables.
// QKV: index (((ng*12 + kc)*2 + kst)*12 + nt)*32 + lane  -> (bh0,bh1,bl0,bl1)
// PRJ: index (((ng*12 + kc)*2 + kst)*4  + nt)*32 + lane
#define QKV_FRAGS (6*12*2*12*32)
#define PRJ_FRAGS (6*12*2*4*32)
__device__ uint4 g_wq[QKV_FRAGS];
__device__ uint4 g_wp[PRJ_FRAGS];

// ---------------- tf32 helpers ----------------
__device__ __forceinline__ uint32_t f2tf(float f) {
    uint32_t u; asm("cvt.rna.tf32.f32 %0, %1;" : "=r"(u) : "f"(f)); return u;
}
__device__ __forceinline__ void mma8(float* d, const uint32_t* a, uint32_t b0, uint32_t b1) {
    asm volatile("mma.sync.aligned.m16n8k8.row.col.f32.tf32.tf32.f32 "
                 "{%0,%1,%2,%3},{%4,%5,%6,%7},{%8,%9},{%0,%1,%2,%3};"
                 : "+f"(d[0]), "+f"(d[1]), "+f"(d[2]), "+f"(d[3])
                 : "r"(a[0]), "r"(a[1]), "r"(a[2]), "r"(a[3]), "r"(b0), "r"(b1));
}

// ---------------------------------------------------------------------------
// Kernel 0: build fragment-ordered tf32 hi/lo weight tables (runs per replay,
// tiny). One thread per fragment-lane.
// ---------------------------------------------------------------------------
__global__ void prep_w_kernel(const float* __restrict__ qkv_w,
                              const float* __restrict__ proj_w)
{
    int i = blockIdx.x * blockDim.x + threadIdx.x;
    if (i < QKV_FRAGS) {
        int lane = i & 31, r = i >> 5;
        int nt = r % 12; r /= 12;
        int kst = r & 1; r >>= 1;
        int kc = r % 12; int ng = r / 12;
        int g = lane >> 2, qd = lane & 3;
        int col = ng * 96 + nt * 8 + g;
        int k0 = kc * 16 + kst * 8 + qd;
        float v0 = qkv_w[col * 192 + k0];
        float v1 = qkv_w[col * 192 + k0 + 4];
        uint32_t h0 = f2tf(v0), l0 = f2tf(v0 - __uint_as_float(h0));
        uint32_t h1 = f2tf(v1), l1 = f2tf(v1 - __uint_as_float(h1));
        g_wq[i] = make_uint4(h0, h1, l0, l1);
    }
    int j = i - QKV_FRAGS;
    if (j >= 0 && j < PRJ_FRAGS) {
        int lane = j & 31, r = j >> 5;
        int nt = r % 4; r /= 4;
        int kst = r & 1; r >>= 1;
        int kc = r % 12; int ng = r / 12;
        int g = lane >> 2, qd = lane & 3;
        int col = ng * 32 + nt * 8 + g;
        int k0 = kc * 16 + kst * 8 + qd;
        float v0 = proj_w[col * 192 + k0];
        float v1 = proj_w[col * 192 + k0 + 4];
        uint32_t h0 = f2tf(v0), l0 = f2tf(v0 - __uint_as_float(h0));
        uint32_t h1 = f2tf(v1), l1 = f2tf(v1 - __uint_as_float(h1));
        g_wp[j] = make_uint4(h0, h1, l0, l1);
    }
}

// ---------------------------------------------------------------------------
// Kernel 1: continuous relative position bias (tiny MLP), one block.
// ---------------------------------------------------------------------------
__global__ void cpb_kernel(const float* __restrict__ w1,
                           const float* __restrict__ b1,
                           const float* __restrict__ w2)
{
    __shared__ float rpb[225 * NH];
    const int t = threadIdx.x;
    const float inv_log2_8 = 1.0f / 3.0f;

    for (int e = t; e < 225 * NH; e += 256) {
        int te = e / NH, h = e % NH;
        int i = te / 15, j = te % 15;
        float cy = (float)(i - 7) * (8.0f / 7.0f);
        float cx = (float)(j - 7) * (8.0f / 7.0f);
        cy = copysignf(log2f(fabsf(cy) + 1.0f), cy) * inv_log2_8;
        cx = copysignf(log2f(fabsf(cx) + 1.0f), cx) * inv_log2_8;
        float acc = 0.0f;
        for (int k = 0; k < CPBH; k++) {
            float hm = cy * w1[2 * k] + cx * w1[2 * k + 1] + b1[k];
            hm = fmaxf(hm, 0.0f);
            acc += hm * w2[h * CPBH + k];
        }
        rpb[te * NH + h] = acc;
    }
    __syncthreads();

    for (int e = t; e < NH * NSEQ * NSEQ; e += 256) {
        int h = e / (NSEQ * NSEQ);
        int rr = e % (NSEQ * NSEQ);
        int i = rr / NSEQ, j = rr % NSEQ;
        int dy = (i >> 3) - (j >> 3) + 7;
        int dx = (i & 7) - (j & 7) + 7;
        float v = rpb[(dy * 15 + dx) * NH + h];
        g_bias[e] = 16.0f / (1.0f + expf(-v));
    }
}

// ---------------------------------------------------------------------------
// Kernel 2: fused window attention; GEMMs on tensor cores, weights from
// precomputed fragment tables (no staging, no inner barriers).
// ---------------------------------------------------------------------------
__global__ __launch_bounds__(NTHREADS)
void win_attn_kernel(const float* __restrict__ x,
                     const float* __restrict__ mask,
                     const float* __restrict__ q_bias,
                     const float* __restrict__ v_bias,
                     const float* __restrict__ logit_scale,
                     const float* __restrict__ proj_b,
                     float* __restrict__ out)
{
    extern __shared__ float sm[];
    float* sx     = sm + SX_OFF;
    float* sq     = sm + SQ_OFF;
    float* sk     = sm + SK_OFF;
    float* sv     = sm + SV_OFF;
    float* sinvq  = sm + SIQ_OFF;
    float* sinvk  = sm + SIK_OFF;
    float* sscale = sm + SSC_OFF;

    const int t = threadIdx.x;
    const int b = blockIdx.x;
    const int widx = b & (NW - 1);
    const float* xb = x + (size_t)b * NSEQ * CDIM;

    const int w    = t >> 5;
    const int lane = t & 31;
    const int g    = lane >> 2;
    const int qd   = lane & 3;

    // -------- load x window into smem (stride 196) --------
    for (int idx = t; idx < NSEQ * CDIM / 4; idx += NTHREADS) {
        float4 v4 = ((const float4*)xb)[idx];
        int n = (idx * 4) / CDIM;
        int k = (idx * 4) % CDIM;
        *(float4*)&sx[n * SXS + k] = v4;
    }
    if (t < NH) sscale[t] = __expf(fminf(logit_scale[t], 4.60517019f)); // ln(100)
    __syncthreads();

    // ================= Phase 1: QKV GEMM (64 x 576 x 192), 3xTF32 ==========
    {
        const int mg = w & 1;
        const int ng = w >> 1;
        const int cb = ng * 96;

        float acc[2][12][4];
        #pragma unroll
        for (int a = 0; a < 2; a++)
            #pragma unroll
            for (int nt = 0; nt < 12; nt++)
                #pragma unroll
                for (int e = 0; e < 4; e++) acc[a][nt][e] = 0.0f;

        for (int kc = 0; kc < 12; kc++) {
            #pragma unroll
            for (int kst = 0; kst < 2; kst++) {
                // A fragments (x rows), tf32 hi/lo
                uint32_t ahi[2][4], alo[2][4];
                #pragma unroll
                for (int mt = 0; mt < 2; mt++) {
                    const float* xr = &sx[(mg * 32 + mt * 16 + g) * SXS + kc * 16 + kst * 8 + qd];
                    float v0 = xr[0];
                    float v1 = xr[4];
                    float v2 = xr[8 * SXS];
                    float v3 = xr[8 * SXS + 4];
                    ahi[mt][0] = f2tf(v0); alo[mt][0] = f2tf(v0 - __uint_as_float(ahi[mt][0]));
                    ahi[mt][1] = f2tf(v2); alo[mt][1] = f2tf(v2 - __uint_as_float(ahi[mt][1]));
                    ahi[mt][2] = f2tf(v1); alo[mt][2] = f2tf(v1 - __uint_as_float(ahi[mt][2]));
                    ahi[mt][3] = f2tf(v3); alo[mt][3] = f2tf(v3 - __uint_as_float(ahi[mt][3]));
                }
                const uint4* wrow = &g_wq[(((ng * 12 + kc) * 2 + kst) * 12) * 32 + lane];
                #pragma unroll
                for (int nt = 0; nt < 12; nt++) {
                    uint4 bb = wrow[nt * 32];
                    #pragma unroll
                    for (int mt = 0; mt < 2; mt++) {
                        mma8(acc[mt][nt], ahi[mt], bb.x, bb.y);
                        mma8(acc[mt][nt], ahi[mt], bb.z, bb.w);
                        mma8(acc[mt][nt], alo[mt], bb.x, bb.y);
                    }
                }
            }
        }

        // scatter accumulators to sq / sk / sv (s constant per warp)
        const int s = ng >> 1;   // 0=q, 1=k, 2=v
        #pragma unroll
        for (int mt = 0; mt < 2; mt++) {
            #pragma unroll
            for (int nt = 0; nt < 12; nt++) {
                int col0 = cb + nt * 8 + qd * 2;
                int rem = col0 - s * 192;
                int h = rem >> 5, d = rem & 31;
                #pragma unroll
                for (int rr = 0; rr < 2; rr++) {
                    int n = mg * 32 + mt * 16 + g + rr * 8;
                    float v0 = acc[mt][nt][rr * 2 + 0];
                    float v1 = acc[mt][nt][rr * 2 + 1];
                    if (s == 0) {
                        sq[(h * 64 + n) * 33 + d]     = v0 + q_bias[rem];
                        sq[(h * 64 + n) * 33 + d + 1] = v1 + q_bias[rem + 1];
                    } else if (s == 1) {
                        sk[(h * 64 + n) * 32 + d]     = v0;
                        sk[(h * 64 + n) * 32 + d + 1] = v1;
                    } else {
                        sv[(h * 64 + n) * 32 + d]     = v0 + v_bias[rem];
                        sv[(h * 64 + n) * 32 + d + 1] = v1 + v_bias[rem + 1];
                    }
                }
            }
        }
    }
    __syncthreads();

    // -------- Phase 1b: per-row inverse norms of q and k --------
    {
        for (int task = w; task < 24; task += 12) {
            int typ   = task / 12;
            int hh    = (task % 12) >> 1;
            int rbase = (task & 1) * 32;
            for (int r = 0; r < 32; r++) {
                int row = hh * 64 + rbase + r;
                float vq = typ ? sk[row * 32 + lane] : sq[row * 33 + lane];
                float ss = vq * vq;
                #pragma unroll
                for (int off = 16; off; off >>= 1)
                    ss += __shfl_xor_sync(0xffffffffu, ss, off);
                if (lane == 0) {
                    float inv = 1.0f / fmaxf(sqrtf(ss), 1e-12f);
                    if (typ) sinvk[row] = inv; else sinvq[row] = inv;
                }
            }
        }
    }
    __syncthreads();

    // -------- Phase 2: per-warp per-head attention, S row in registers --------
    {
        int h = w >> 1;
        int r = (w & 1) * 32 + lane;
        int row = h * 64 + r;

        float qv[32];
        float qs = sinvq[row] * sscale[h];
        #pragma unroll
        for (int d = 0; d < 32; d++) qv[d] = sq[row * 33 + d] * qs;

        float S[64];
        const float* biasrow = &g_bias[(h * 64 + r) * 64];
        const float* maskrow = &mask[((size_t)widx * 64 + r) * 64];

        #pragma unroll
        for (int m = 0; m < 64; m++) {
            const float4* kp = (const float4*)&sk[(h * 64 + m) * 32];
            float dot = 0.0f;
            #pragma unroll
            for (int q4 = 0; q4 < 8; q4++) {
                float4 kk = kp[q4];
                dot += qv[q4 * 4 + 0] * kk.x + qv[q4 * 4 + 1] * kk.y
                     + qv[q4 * 4 + 2] * kk.z + qv[q4 * 4 + 3] * kk.w;
            }
            S[m] = dot * sinvk[h * 64 + m] + biasrow[m] + maskrow[m];
        }

        float mx = -1e30f;
        #pragma unroll
        for (int m = 0; m < 64; m++) mx = fmaxf(mx, S[m]);
        float sum = 0.0f;
        #pragma unroll
        for (int m = 0; m < 64; m++) { S[m] = __expf(S[m] - mx); sum += S[m]; }
        float rs = 1.0f / sum;

        float o[32];
        #pragma unroll
        for (int d = 0; d < 32; d++) o[d] = 0.0f;
        #pragma unroll
        for (int m = 0; m < 64; m++) {
            float p = S[m];
            const float4* vp = (const float4*)&sv[(h * 64 + m) * 32];
            #pragma unroll
            for (int q4 = 0; q4 < 8; q4++) {
                float4 vv = vp[q4];
                o[q4 * 4 + 0] += p * vv.x; o[q4 * 4 + 1] += p * vv.y;
                o[q4 * 4 + 2] += p * vv.z; o[q4 * 4 + 3] += p * vv.w;
            }
        }
        #pragma unroll
        for (int d = 0; d < 32; d++)
            sx[r * SXS + h * 32 + d] = o[d] * rs;
    }
    __syncthreads();

    // ================= Phase 3: proj GEMM (64 x 192 x 192), 3xTF32 ==========
    {
        const int mg = w & 1;
        const int ng = w >> 1;
        const int cb = ng * 32;

        float acc[2][4][4];
        #pragma unroll
        for (int a = 0; a < 2; a++)
            #pragma unroll
            for (int nt = 0; nt < 4; nt++)
                #pragma unroll
                for (int e = 0; e < 4; e++) acc[a][nt][e] = 0.0f;

        for (int kc = 0; kc < 12; kc++) {
            #pragma unroll
            for (int kst = 0; kst < 2; kst++) {
                uint32_t ahi[2][4], alo[2][4];
                #pragma unroll
                for (int mt = 0; mt < 2; mt++) {
                    const float* xr = &sx[(mg * 32 + mt * 16 + g) * SXS + kc * 16 + kst * 8 + qd];
                    float v0 = xr[0];
                    float v1 = xr[4];
                    float v2 = xr[8 * SXS];
                    float v3 = xr[8 * SXS + 4];
                    ahi[mt][0] = f2tf(v0); alo[mt][0] = f2tf(v0 - __uint_as_float(ahi[mt][0]));
                    ahi[mt][1] = f2tf(v2); alo[mt][1] = f2tf(v2 - __uint_as_float(ahi[mt][1]));
                    ahi[mt][2] = f2tf(v1); alo[mt][2] = f2tf(v1 - __uint_as_float(ahi[mt][2]));
                    ahi[mt][3] = f2tf(v3); alo[mt][3] = f2tf(v3 - __uint_as_float(ahi[mt][3]));
                }
                const uint4* wrow = &g_wp[(((ng * 12 + kc) * 2 + kst) * 4) * 32 + lane];
                #pragma unroll
                for (int nt = 0; nt < 4; nt++) {
                    uint4 bb = wrow[nt * 32];
                    #pragma unroll
                    for (int mt = 0; mt < 2; mt++) {
                        mma8(acc[mt][nt], ahi[mt], bb.x, bb.y);
                        mma8(acc[mt][nt], ahi[mt], bb.z, bb.w);
                        mma8(acc[mt][nt], alo[mt], bb.x, bb.y);
                    }
                }
            }
        }

        float* ob = out + (size_t)b * NSEQ * CDIM;
        #pragma unroll
        for (int mt = 0; mt < 2; mt++) {
            #pragma unroll
            for (int nt = 0; nt < 4; nt++) {
                int col0 = cb + nt * 8 + qd * 2;
                float pb0 = proj_b[col0], pb1 = proj_b[col0 + 1];
                #pragma unroll
                for (int rr = 0; rr < 2; rr++) {
                    int n = mg * 32 + mt * 16 + g + rr * 8;
                    float2 o2 = make_float2(acc[mt][nt][rr * 2 + 0] + pb0,
                                            acc[mt][nt][rr * 2 + 1] + pb1);
                    *(float2*)&ob[n * 192 + col0] = o2;
                }
            }
        }
    }
}

// ---------------------------------------------------------------------------
extern "C" void kernel_launch(void* const* d_in, const int* in_sizes, int n_in,
                              void* d_out, int out_size)
{
    const float* x           = (const float*)d_in[0];
    const float* mask        = (const float*)d_in[1];
    const float* qkv_w       = (const float*)d_in[2];
    const float* q_bias      = (const float*)d_in[3];
    const float* v_bias      = (const float*)d_in[4];
    const float* logit_scale = (const float*)d_in[5];
    const float* cpb_w1      = (const float*)d_in[6];
    const float* cpb_b1      = (const float*)d_in[7];
    const float* cpb_w2      = (const float*)d_in[8];
    const float* proj_w      = (const float*)d_in[9];
    const float* proj_b      = (const float*)d_in[10];
    float* out = (float*)d_out;

    cudaFuncSetAttribute(win_attn_kernel,
                         cudaFuncAttributeMaxDynamicSharedMemorySize, SMEM_BYTES);

    prep_w_kernel<<<(QKV_FRAGS + PRJ_FRAGS + 255) / 256, 256>>>(qkv_w, proj_w);
    cpb_kernel<<<1, 256>>>(cpb_w1, cpb_b1, cpb_w2);
    win_attn_kernel<<<B_TOT, NTHREADS, SMEM_BYTES>>>(
        x, mask, q_bias, v_bias, logit_scale, proj_b, out);
}

// round 4
// speedup vs baseline: 2.6798x; 1.6821x over previous
#include <cuda_runtime.h>
#include <math.h>
#include <stdint.h>

// Problem constants
#define B_TOT   4096
#define NSEQ    64
#define CDIM    192
#define NH      6
#define NW      64
#define CPBH    512
#define NTHREADS 384

// Shared memory layout (floats). q/k/v stride 33 (conflict-free scalar access).
#define SXS     196
#define SX_OFF  0
#define SQ_OFF  (SX_OFF + 64*SXS)
#define SK_OFF  (SQ_OFF + NH*64*33)
#define SV_OFF  (SK_OFF + NH*64*33)
#define SIQ_OFF (SV_OFF + NH*64*33)
#define SIK_OFF (SIQ_OFF + 384)
#define SSC_OFF (SIK_OFF + 384)
#define SMEM_FLOATS (SSC_OFF + 8)
#define SMEM_BYTES (SMEM_FLOATS * 4)

__device__ float g_bias[NH * NSEQ * NSEQ];
// combined 16*sigmoid(bias)+mask table: [widx][h][row][col]
__device__ float g_bm[(size_t)NW * NH * NSEQ * NSEQ];

// Precomputed fragment-ordered tf32 hi/lo weight tables.
#define QKV_FRAGS (6*12*2*12*32)
#define PRJ_FRAGS (6*12*2*4*32)
__device__ uint4 g_wq[QKV_FRAGS];
__device__ uint4 g_wp[PRJ_FRAGS];

// ---------------- tf32 helpers ----------------
__device__ __forceinline__ uint32_t f2tf(float f) {
    uint32_t u; asm("cvt.rna.tf32.f32 %0, %1;" : "=r"(u) : "f"(f)); return u;
}
__device__ __forceinline__ void mma8(float* d, const uint32_t* a, uint32_t b0, uint32_t b1) {
    asm volatile("mma.sync.aligned.m16n8k8.row.col.f32.tf32.tf32.f32 "
                 "{%0,%1,%2,%3},{%4,%5,%6,%7},{%8,%9},{%0,%1,%2,%3};"
                 : "+f"(d[0]), "+f"(d[1]), "+f"(d[2]), "+f"(d[3])
                 : "r"(a[0]), "r"(a[1]), "r"(a[2]), "r"(a[3]), "r"(b0), "r"(b1));
}
// split a float into tf32 hi/lo
__device__ __forceinline__ void tfsplit(float v, uint32_t& hi, uint32_t& lo) {
    hi = f2tf(v);
    lo = f2tf(v - __uint_as_float(hi));
}

// ---------------------------------------------------------------------------
// Kernel 0: build fragment-ordered tf32 hi/lo weight tables.
// ---------------------------------------------------------------------------
__global__ void prep_w_kernel(const float* __restrict__ qkv_w,
                              const float* __restrict__ proj_w)
{
    int i = blockIdx.x * blockDim.x + threadIdx.x;
    if (i < QKV_FRAGS) {
        int lane = i & 31, r = i >> 5;
        int nt = r % 12; r /= 12;
        int kst = r & 1; r >>= 1;
        int kc = r % 12; int ng = r / 12;
        int g = lane >> 2, qd = lane & 3;
        int col = ng * 96 + nt * 8 + g;
        int k0 = kc * 16 + kst * 8 + qd;
        float v0 = qkv_w[col * 192 + k0];
        float v1 = qkv_w[col * 192 + k0 + 4];
        uint32_t h0, l0, h1, l1;
        tfsplit(v0, h0, l0); tfsplit(v1, h1, l1);
        g_wq[i] = make_uint4(h0, h1, l0, l1);
    }
    int j = i - QKV_FRAGS;
    if (j >= 0 && j < PRJ_FRAGS) {
        int lane = j & 31, r = j >> 5;
        int nt = r % 4; r /= 4;
        int kst = r & 1; r >>= 1;
        int kc = r % 12; int ng = r / 12;
        int g = lane >> 2, qd = lane & 3;
        int col = ng * 32 + nt * 8 + g;
        int k0 = kc * 16 + kst * 8 + qd;
        float v0 = proj_w[col * 192 + k0];
        float v1 = proj_w[col * 192 + k0 + 4];
        uint32_t h0, l0, h1, l1;
        tfsplit(v0, h0, l0); tfsplit(v1, h1, l1);
        g_wp[j] = make_uint4(h0, h1, l0, l1);
    }
}

// ---------------------------------------------------------------------------
// Kernel 1: continuous relative position bias (tiny MLP), one block.
// ---------------------------------------------------------------------------
__global__ void cpb_kernel(const float* __restrict__ w1,
                           const float* __restrict__ b1,
                           const float* __restrict__ w2)
{
    __shared__ float rpb[225 * NH];
    const int t = threadIdx.x;
    const float inv_log2_8 = 1.0f / 3.0f;

    for (int e = t; e < 225 * NH; e += 256) {
        int te = e / NH, h = e % NH;
        int i = te / 15, j = te % 15;
        float cy = (float)(i - 7) * (8.0f / 7.0f);
        float cx = (float)(j - 7) * (8.0f / 7.0f);
        cy = copysignf(log2f(fabsf(cy) + 1.0f), cy) * inv_log2_8;
        cx = copysignf(log2f(fabsf(cx) + 1.0f), cx) * inv_log2_8;
        float acc = 0.0f;
        for (int k = 0; k < CPBH; k++) {
            float hm = cy * w1[2 * k] + cx * w1[2 * k + 1] + b1[k];
            hm = fmaxf(hm, 0.0f);
            acc += hm * w2[h * CPBH + k];
        }
        rpb[te * NH + h] = acc;
    }
    __syncthreads();

    for (int e = t; e < NH * NSEQ * NSEQ; e += 256) {
        int h = e / (NSEQ * NSEQ);
        int rr = e % (NSEQ * NSEQ);
        int i = rr / NSEQ, j = rr % NSEQ;
        int dy = (i >> 3) - (j >> 3) + 7;
        int dx = (i & 7) - (j & 7) + 7;
        float v = rpb[(dy * 15 + dx) * NH + h];
        g_bias[e] = 16.0f / (1.0f + expf(-v));
    }
}

// ---------------------------------------------------------------------------
// Kernel 1b: combine bias + mask into per-(widx,h) table.
// ---------------------------------------------------------------------------
__global__ void bm_kernel(const float* __restrict__ mask)
{
    int blk = blockIdx.x;            // widx*NH + h
    int widx = blk / NH, h = blk % NH;
    const float* mrow = mask + (size_t)widx * NSEQ * NSEQ;
    const float* brow = g_bias + h * NSEQ * NSEQ;
    float* dst = g_bm + (size_t)blk * NSEQ * NSEQ;
    for (int i = threadIdx.x; i < NSEQ * NSEQ; i += 256)
        dst[i] = brow[i] + mrow[i];
}

// ---------------------------------------------------------------------------
// Kernel 2: fully fused window attention, all GEMMs on tensor cores.
// ---------------------------------------------------------------------------
__global__ __launch_bounds__(NTHREADS)
void win_attn_kernel(const float* __restrict__ x,
                     const float* __restrict__ q_bias,
                     const float* __restrict__ v_bias,
                     const float* __restrict__ logit_scale,
                     const float* __restrict__ proj_b,
                     float* __restrict__ out)
{
    extern __shared__ float sm[];
    float* sx     = sm + SX_OFF;
    float* sq     = sm + SQ_OFF;
    float* sk     = sm + SK_OFF;
    float* sv     = sm + SV_OFF;
    float* sinvq  = sm + SIQ_OFF;
    float* sinvk  = sm + SIK_OFF;
    float* sscale = sm + SSC_OFF;

    const int t = threadIdx.x;
    const int b = blockIdx.x;
    const int widx = b & (NW - 1);
    const float* xb = x + (size_t)b * NSEQ * CDIM;

    const int w    = t >> 5;
    const int lane = t & 31;
    const int g    = lane >> 2;
    const int qd   = lane & 3;

    // -------- load x window into smem (stride 196) --------
    for (int idx = t; idx < NSEQ * CDIM / 4; idx += NTHREADS) {
        float4 v4 = ((const float4*)xb)[idx];
        int n = (idx * 4) / CDIM;
        int k = (idx * 4) % CDIM;
        *(float4*)&sx[n * SXS + k] = v4;
    }
    if (t < NH) sscale[t] = __expf(fminf(logit_scale[t], 4.60517019f)); // ln(100)
    __syncthreads();

    // ================= Phase 1: QKV GEMM (64 x 576 x 192), 3xTF32 ==========
    {
        const int mg = w & 1;
        const int ng = w >> 1;
        const int cb = ng * 96;

        float acc[2][12][4];
        #pragma unroll
        for (int a = 0; a < 2; a++)
            #pragma unroll
            for (int nt = 0; nt < 12; nt++)
                #pragma unroll
                for (int e = 0; e < 4; e++) acc[a][nt][e] = 0.0f;

        for (int kc = 0; kc < 12; kc++) {
            #pragma unroll
            for (int kst = 0; kst < 2; kst++) {
                uint32_t ahi[2][4], alo[2][4];
                #pragma unroll
                for (int mt = 0; mt < 2; mt++) {
                    const float* xr = &sx[(mg * 32 + mt * 16 + g) * SXS + kc * 16 + kst * 8 + qd];
                    tfsplit(xr[0],           ahi[mt][0], alo[mt][0]);
                    tfsplit(xr[8 * SXS],     ahi[mt][1], alo[mt][1]);
                    tfsplit(xr[4],           ahi[mt][2], alo[mt][2]);
                    tfsplit(xr[8 * SXS + 4], ahi[mt][3], alo[mt][3]);
                }
                const uint4* wrow = &g_wq[(((ng * 12 + kc) * 2 + kst) * 12) * 32 + lane];
                #pragma unroll
                for (int nt = 0; nt < 12; nt++) {
                    uint4 bb = wrow[nt * 32];
                    #pragma unroll
                    for (int mt = 0; mt < 2; mt++) {
                        mma8(acc[mt][nt], ahi[mt], bb.x, bb.y);
                        mma8(acc[mt][nt], ahi[mt], bb.z, bb.w);
                        mma8(acc[mt][nt], alo[mt], bb.x, bb.y);
                    }
                }
            }
        }

        // scatter accumulators to sq / sk / sv; fold in row-norm partials
        const int s = ng >> 1;   // 0=q, 1=k, 2=v
        float ss[2][2][3];
        #pragma unroll
        for (int a = 0; a < 2; a++)
            #pragma unroll
            for (int c = 0; c < 2; c++)
                #pragma unroll
                for (int hh = 0; hh < 3; hh++) ss[a][c][hh] = 0.0f;

        #pragma unroll
        for (int mt = 0; mt < 2; mt++) {
            #pragma unroll
            for (int nt = 0; nt < 12; nt++) {
                int col0 = cb + nt * 8 + qd * 2;
                int rem = col0 - s * 192;
                int h = rem >> 5, d = rem & 31;
                int hs = nt >> 2;
                #pragma unroll
                for (int rr = 0; rr < 2; rr++) {
                    int n = mg * 32 + mt * 16 + g + rr * 8;
                    float v0 = acc[mt][nt][rr * 2 + 0];
                    float v1 = acc[mt][nt][rr * 2 + 1];
                    if (s == 0) {
                        v0 += q_bias[rem]; v1 += q_bias[rem + 1];
                        ss[mt][rr][hs] += v0 * v0 + v1 * v1;
                        sq[(h * 64 + n) * 33 + d]     = v0;
                        sq[(h * 64 + n) * 33 + d + 1] = v1;
                    } else if (s == 1) {
                        ss[mt][rr][hs] += v0 * v0 + v1 * v1;
                        sk[(h * 64 + n) * 33 + d]     = v0;
                        sk[(h * 64 + n) * 33 + d + 1] = v1;
                    } else {
                        sv[(h * 64 + n) * 33 + d]     = v0 + v_bias[rem];
                        sv[(h * 64 + n) * 33 + d + 1] = v1 + v_bias[rem + 1];
                    }
                }
            }
        }

        if (s < 2) {
            #pragma unroll
            for (int mt = 0; mt < 2; mt++)
                #pragma unroll
                for (int rr = 0; rr < 2; rr++)
                    #pragma unroll
                    for (int hs = 0; hs < 3; hs++) {
                        float tot = ss[mt][rr][hs];
                        tot += __shfl_xor_sync(0xffffffffu, tot, 1);
                        tot += __shfl_xor_sync(0xffffffffu, tot, 2);
                        if (qd == 0) {
                            int n = mg * 32 + mt * 16 + g + rr * 8;
                            int hh = (ng & 1) * 3 + hs;
                            float inv = 1.0f / fmaxf(sqrtf(tot), 1e-12f);
                            if (s == 0) sinvq[hh * 64 + n] = inv;
                            else        sinvk[hh * 64 + n] = inv;
                        }
                    }
        }
    }
    __syncthreads();

    // ============ Phase 2: attention via 3xTF32 mma (S, softmax, PV) =======
    {
        const int h  = w >> 1;
        const int m0 = (w & 1) * 32;

        float qsc[2][2], ksc[8];
        #pragma unroll
        for (int mt = 0; mt < 2; mt++) {
            qsc[mt][0] = sinvq[h * 64 + m0 + mt * 16 + g]     * sscale[h];
            qsc[mt][1] = sinvq[h * 64 + m0 + mt * 16 + g + 8] * sscale[h];
        }
        #pragma unroll
        for (int nt = 0; nt < 8; nt++) ksc[nt] = sinvk[h * 64 + nt * 8 + g];

        // ---- S = qn @ kn^T   (m=32, n=64, k=32) ----
        float p[2][8][4];
        #pragma unroll
        for (int mt = 0; mt < 2; mt++)
            #pragma unroll
            for (int nt = 0; nt < 8; nt++)
                #pragma unroll
                for (int e = 0; e < 4; e++) p[mt][nt][e] = 0.0f;

        #pragma unroll
        for (int kt = 0; kt < 4; kt++) {
            uint32_t ahi[2][4], alo[2][4];
            #pragma unroll
            for (int mt = 0; mt < 2; mt++) {
                const float* qr = &sq[(h * 64 + m0 + mt * 16 + g) * 33 + kt * 8 + qd];
                tfsplit(qr[0]          * qsc[mt][0], ahi[mt][0], alo[mt][0]);
                tfsplit(qr[8 * 33]     * qsc[mt][1], ahi[mt][1], alo[mt][1]);
                tfsplit(qr[4]          * qsc[mt][0], ahi[mt][2], alo[mt][2]);
                tfsplit(qr[8 * 33 + 4] * qsc[mt][1], ahi[mt][3], alo[mt][3]);
            }
            #pragma unroll
            for (int nt = 0; nt < 8; nt++) {
                const float* kr = &sk[(h * 64 + nt * 8 + g) * 33 + kt * 8 + qd];
                uint32_t bh0, bl0, bh1, bl1;
                tfsplit(kr[0] * ksc[nt], bh0, bl0);
                tfsplit(kr[4] * ksc[nt], bh1, bl1);
                #pragma unroll
                for (int mt = 0; mt < 2; mt++) {
                    mma8(p[mt][nt], ahi[mt], bh0, bh1);
                    mma8(p[mt][nt], ahi[mt], bl0, bl1);
                    mma8(p[mt][nt], alo[mt], bh0, bh1);
                }
            }
        }

        // ---- bias+mask, softmax over rows (row spread across qd group) ----
        const float* bmb = &g_bm[((size_t)widx * NH + h) * NSEQ * NSEQ];
        #pragma unroll
        for (int mt = 0; mt < 2; mt++) {
            #pragma unroll
            for (int r2 = 0; r2 < 2; r2++) {
                int row = m0 + mt * 16 + g + 8 * r2;
                const float* bmr = bmb + row * 64 + qd * 2;
                float mx = -1e30f;
                #pragma unroll
                for (int nt = 0; nt < 8; nt++) {
                    float2 bmv = *(const float2*)&bmr[nt * 8];
                    p[mt][nt][r2 * 2 + 0] += bmv.x;
                    p[mt][nt][r2 * 2 + 1] += bmv.y;
                    mx = fmaxf(mx, fmaxf(p[mt][nt][r2 * 2], p[mt][nt][r2 * 2 + 1]));
                }
                mx = fmaxf(mx, __shfl_xor_sync(0xffffffffu, mx, 1));
                mx = fmaxf(mx, __shfl_xor_sync(0xffffffffu, mx, 2));
                float sum = 0.0f;
                #pragma unroll
                for (int nt = 0; nt < 8; nt++) {
                    float e0 = __expf(p[mt][nt][r2 * 2 + 0] - mx);
                    float e1 = __expf(p[mt][nt][r2 * 2 + 1] - mx);
                    p[mt][nt][r2 * 2 + 0] = e0;
                    p[mt][nt][r2 * 2 + 1] = e1;
                    sum += e0 + e1;
                }
                sum += __shfl_xor_sync(0xffffffffu, sum, 1);
                sum += __shfl_xor_sync(0xffffffffu, sum, 2);
                float rs = 1.0f / sum;
                #pragma unroll
                for (int nt = 0; nt < 8; nt++) {
                    p[mt][nt][r2 * 2 + 0] *= rs;
                    p[mt][nt][r2 * 2 + 1] *= rs;
                }
            }
        }

        // ---- PV (m=32, n=32, k=64); P acc->A via intra-quad shfl ----
        float o[2][4][4];
        #pragma unroll
        for (int mt = 0; mt < 2; mt++)
            #pragma unroll
            for (int nt = 0; nt < 4; nt++)
                #pragma unroll
                for (int e = 0; e < 4; e++) o[mt][nt][e] = 0.0f;

        const int s0 = g * 4 + (qd >> 1);
        const int s1 = s0 + 2;
        const bool odd = (qd & 1);

        #pragma unroll
        for (int kt = 0; kt < 8; kt++) {
            uint32_t phi[2][4], plo[2][4];
            #pragma unroll
            for (int mt = 0; mt < 2; mt++) {
                float e0 = __shfl_sync(0xffffffffu, p[mt][kt][0], s0);
                float e1 = __shfl_sync(0xffffffffu, p[mt][kt][1], s0);
                float e2 = __shfl_sync(0xffffffffu, p[mt][kt][2], s0);
                float e3 = __shfl_sync(0xffffffffu, p[mt][kt][3], s0);
                float f0 = __shfl_sync(0xffffffffu, p[mt][kt][0], s1);
                float f1 = __shfl_sync(0xffffffffu, p[mt][kt][1], s1);
                float f2 = __shfl_sync(0xffffffffu, p[mt][kt][2], s1);
                float f3 = __shfl_sync(0xffffffffu, p[mt][kt][3], s1);
                float a0 = odd ? e1 : e0;
                float a1 = odd ? e3 : e2;
                float a2 = odd ? f1 : f0;
                float a3 = odd ? f3 : f2;
                tfsplit(a0, phi[mt][0], plo[mt][0]);
                tfsplit(a1, phi[mt][1], plo[mt][1]);
                tfsplit(a2, phi[mt][2], plo[mt][2]);
                tfsplit(a3, phi[mt][3], plo[mt][3]);
            }
            #pragma unroll
            for (int nt = 0; nt < 4; nt++) {
                float v0 = sv[(h * 64 + kt * 8 + qd) * 33     + nt * 8 + g];
                float v1 = sv[(h * 64 + kt * 8 + qd + 4) * 33 + nt * 8 + g];
                uint32_t vh0, vl0, vh1, vl1;
                tfsplit(v0, vh0, vl0);
                tfsplit(v1, vh1, vl1);
                #pragma unroll
                for (int mt = 0; mt < 2; mt++) {
                    mma8(o[mt][nt], phi[mt], vh0, vh1);
                    mma8(o[mt][nt], phi[mt], vl0, vl1);
                    mma8(o[mt][nt], plo[mt], vh0, vh1);
                }
            }
        }

        // ---- write attention output into sx [row][h*32+d] ----
        #pragma unroll
        for (int mt = 0; mt < 2; mt++) {
            #pragma unroll
            for (int nt = 0; nt < 4; nt++) {
                int col = h * 32 + nt * 8 + qd * 2;
                #pragma unroll
                for (int r2 = 0; r2 < 2; r2++) {
                    int row = m0 + mt * 16 + g + 8 * r2;
                    *(float2*)&sx[row * SXS + col] =
                        make_float2(o[mt][nt][r2 * 2 + 0], o[mt][nt][r2 * 2 + 1]);
                }
            }
        }
    }
    __syncthreads();

    // ================= Phase 3: proj GEMM (64 x 192 x 192), 3xTF32 ==========
    {
        const int mg = w & 1;
        const int ng = w >> 1;
        const int cb = ng * 32;

        float acc[2][4][4];
        #pragma unroll
        for (int a = 0; a < 2; a++)
            #pragma unroll
            for (int nt = 0; nt < 4; nt++)
                #pragma unroll
                for (int e = 0; e < 4; e++) acc[a][nt][e] = 0.0f;

        for (int kc = 0; kc < 12; kc++) {
            #pragma unroll
            for (int kst = 0; kst < 2; kst++) {
                uint32_t ahi[2][4], alo[2][4];
                #pragma unroll
                for (int mt = 0; mt < 2; mt++) {
                    const float* xr = &sx[(mg * 32 + mt * 16 + g) * SXS + kc * 16 + kst * 8 + qd];
                    tfsplit(xr[0],           ahi[mt][0], alo[mt][0]);
                    tfsplit(xr[8 * SXS],     ahi[mt][1], alo[mt][1]);
                    tfsplit(xr[4],           ahi[mt][2], alo[mt][2]);
                    tfsplit(xr[8 * SXS + 4], ahi[mt][3], alo[mt][3]);
                }
                const uint4* wrow = &g_wp[(((ng * 12 + kc) * 2 + kst) * 4) * 32 + lane];
                #pragma unroll
                for (int nt = 0; nt < 4; nt++) {
                    uint4 bb = wrow[nt * 32];
                    #pragma unroll
                    for (int mt = 0; mt < 2; mt++) {
                        mma8(acc[mt][nt], ahi[mt], bb.x, bb.y);
                        mma8(acc[mt][nt], ahi[mt], bb.z, bb.w);
                        mma8(acc[mt][nt], alo[mt], bb.x, bb.y);
                    }
                }
            }
        }

        float* ob = out + (size_t)b * NSEQ * CDIM;
        #pragma unroll
        for (int mt = 0; mt < 2; mt++) {
            #pragma unroll
            for (int nt = 0; nt < 4; nt++) {
                int col0 = cb + nt * 8 + qd * 2;
                float pb0 = proj_b[col0], pb1 = proj_b[col0 + 1];
                #pragma unroll
                for (int rr = 0; rr < 2; rr++) {
                    int n = mg * 32 + mt * 16 + g + rr * 8;
                    float2 o2 = make_float2(acc[mt][nt][rr * 2 + 0] + pb0,
                                            acc[mt][nt][rr * 2 + 1] + pb1);
                    *(float2*)&ob[n * 192 + col0] = o2;
                }
            }
        }
    }
}

// ---------------------------------------------------------------------------
extern "C" void kernel_launch(void* const* d_in, const int* in_sizes, int n_in,
                              void* d_out, int out_size)
{
    const float* x           = (const float*)d_in[0];
    const float* mask        = (const float*)d_in[1];
    const float* qkv_w       = (const float*)d_in[2];
    const float* q_bias      = (const float*)d_in[3];
    const float* v_bias      = (const float*)d_in[4];
    const float* logit_scale = (const float*)d_in[5];
    const float* cpb_w1      = (const float*)d_in[6];
    const float* cpb_b1      = (const float*)d_in[7];
    const float* cpb_w2      = (const float*)d_in[8];
    const float* proj_w      = (const float*)d_in[9];
    const float* proj_b      = (const float*)d_in[10];
    float* out = (float*)d_out;

    cudaFuncSetAttribute(win_attn_kernel,
                         cudaFuncAttributeMaxDynamicSharedMemorySize, SMEM_BYTES);

    prep_w_kernel<<<(QKV_FRAGS + PRJ_FRAGS + 255) / 256, 256>>>(qkv_w, proj_w);
    cpb_kernel<<<1, 256>>>(cpb_w1, cpb_b1, cpb_w2);
    bm_kernel<<<NW * NH, 256>>>(mask);
    win_attn_kernel<<<B_TOT, NTHREADS, SMEM_BYTES>>>(
        x, q_bias, v_bias, logit_scale, proj_b, out);
}

// round 5
// speedup vs baseline: 2.6980x; 1.0068x over previous
#include <cuda_runtime.h>
#include <math.h>
#include <stdint.h>

// Problem constants
#define B_TOT   4096
#define NSEQ    64
#define CDIM    192
#define NH      6
#define NW      64
#define CPBH    512
#define NTHREADS 384

// Shared memory layout (floats). q/k/v stride 33 (conflict-free scalar access).
#define SXS     196
#define SX_OFF  0
#define SQ_OFF  (SX_OFF + 64*SXS)
#define SK_OFF  (SQ_OFF + NH*64*33)
#define SV_OFF  (SK_OFF + NH*64*33)
#define SIQ_OFF (SV_OFF + NH*64*33)
#define SIK_OFF (SIQ_OFF + 384)
#define SSC_OFF (SIK_OFF + 384)
#define SMEM_FLOATS (SSC_OFF + 8)
#define SMEM_BYTES (SMEM_FLOATS * 4)

__device__ float g_bias[NH * NSEQ * NSEQ];
// combined 16*sigmoid(bias)+mask table: [widx][h][row][col]
__device__ float g_bm[(size_t)NW * NH * NSEQ * NSEQ];

// Precomputed fragment-ordered tf32 hi/lo weight tables.
#define QKV_FRAGS (6*12*2*12*32)
#define PRJ_FRAGS (6*12*2*4*32)
__device__ uint4 g_wq[QKV_FRAGS];
__device__ uint4 g_wp[PRJ_FRAGS];

// ---------------- tf32 helpers ----------------
__device__ __forceinline__ uint32_t f2tf(float f) {
    uint32_t u; asm("cvt.rna.tf32.f32 %0, %1;" : "=r"(u) : "f"(f)); return u;
}
__device__ __forceinline__ void mma8(float* d, const uint32_t* a, uint32_t b0, uint32_t b1) {
    asm volatile("mma.sync.aligned.m16n8k8.row.col.f32.tf32.tf32.f32 "
                 "{%0,%1,%2,%3},{%4,%5,%6,%7},{%8,%9},{%0,%1,%2,%3};"
                 : "+f"(d[0]), "+f"(d[1]), "+f"(d[2]), "+f"(d[3])
                 : "r"(a[0]), "r"(a[1]), "r"(a[2]), "r"(a[3]), "r"(b0), "r"(b1));
}
// split a float into tf32 hi/lo
__device__ __forceinline__ void tfsplit(float v, uint32_t& hi, uint32_t& lo) {
    hi = f2tf(v);
    lo = f2tf(v - __uint_as_float(hi));
}

// ---------------------------------------------------------------------------
// Kernel 0: build fragment-ordered tf32 hi/lo weight tables.
// ---------------------------------------------------------------------------
__global__ void prep_w_kernel(const float* __restrict__ qkv_w,
                              const float* __restrict__ proj_w)
{
    int i = blockIdx.x * blockDim.x + threadIdx.x;
    if (i < QKV_FRAGS) {
        int lane = i & 31, r = i >> 5;
        int nt = r % 12; r /= 12;
        int kst = r & 1; r >>= 1;
        int kc = r % 12; int ng = r / 12;
        int g = lane >> 2, qd = lane & 3;
        int col = ng * 96 + nt * 8 + g;
        int k0 = kc * 16 + kst * 8 + qd;
        float v0 = qkv_w[col * 192 + k0];
        float v1 = qkv_w[col * 192 + k0 + 4];
        uint32_t h0, l0, h1, l1;
        tfsplit(v0, h0, l0); tfsplit(v1, h1, l1);
        g_wq[i] = make_uint4(h0, h1, l0, l1);
    }
    int j = i - QKV_FRAGS;
    if (j >= 0 && j < PRJ_FRAGS) {
        int lane = j & 31, r = j >> 5;
        int nt = r % 4; r /= 4;
        int kst = r & 1; r >>= 1;
        int kc = r % 12; int ng = r / 12;
        int g = lane >> 2, qd = lane & 3;
        int col = ng * 32 + nt * 8 + g;
        int k0 = kc * 16 + kst * 8 + qd;
        float v0 = proj_w[col * 192 + k0];
        float v1 = proj_w[col * 192 + k0 + 4];
        uint32_t h0, l0, h1, l1;
        tfsplit(v0, h0, l0); tfsplit(v1, h1, l1);
        g_wp[j] = make_uint4(h0, h1, l0, l1);
    }
}

// ---------------------------------------------------------------------------
// Kernel 1: continuous relative position bias (tiny MLP), one block.
// ---------------------------------------------------------------------------
__global__ void cpb_kernel(const float* __restrict__ w1,
                           const float* __restrict__ b1,
                           const float* __restrict__ w2)
{
    __shared__ float rpb[225 * NH];
    const int t = threadIdx.x;
    const float inv_log2_8 = 1.0f / 3.0f;

    for (int e = t; e < 225 * NH; e += 256) {
        int te = e / NH, h = e % NH;
        int i = te / 15, j = te % 15;
        float cy = (float)(i - 7) * (8.0f / 7.0f);
        float cx = (float)(j - 7) * (8.0f / 7.0f);
        cy = copysignf(log2f(fabsf(cy) + 1.0f), cy) * inv_log2_8;
        cx = copysignf(log2f(fabsf(cx) + 1.0f), cx) * inv_log2_8;
        float acc = 0.0f;
        for (int k = 0; k < CPBH; k++) {
            float hm = cy * w1[2 * k] + cx * w1[2 * k + 1] + b1[k];
            hm = fmaxf(hm, 0.0f);
            acc += hm * w2[h * CPBH + k];
        }
        rpb[te * NH + h] = acc;
    }
    __syncthreads();

    for (int e = t; e < NH * NSEQ * NSEQ; e += 256) {
        int h = e / (NSEQ * NSEQ);
        int rr = e % (NSEQ * NSEQ);
        int i = rr / NSEQ, j = rr % NSEQ;
        int dy = (i >> 3) - (j >> 3) + 7;
        int dx = (i & 7) - (j & 7) + 7;
        float v = rpb[(dy * 15 + dx) * NH + h];
        g_bias[e] = 16.0f / (1.0f + expf(-v));
    }
}

// ---------------------------------------------------------------------------
// Kernel 1b: combine bias + mask into per-(widx,h) table.
// ---------------------------------------------------------------------------
__global__ void bm_kernel(const float* __restrict__ mask)
{
    int blk = blockIdx.x;            // widx*NH + h
    int widx = blk / NH, h = blk % NH;
    const float* mrow = mask + (size_t)widx * NSEQ * NSEQ;
    const float* brow = g_bias + h * NSEQ * NSEQ;
    float* dst = g_bm + (size_t)blk * NSEQ * NSEQ;
    for (int i = threadIdx.x; i < NSEQ * NSEQ; i += 256)
        dst[i] = brow[i] + mrow[i];
}

// ---------------------------------------------------------------------------
// Kernel 2: fully fused window attention, all GEMMs on tensor cores.
// ---------------------------------------------------------------------------
__global__ __launch_bounds__(NTHREADS)
void win_attn_kernel(const float* __restrict__ x,
                     const float* __restrict__ q_bias,
                     const float* __restrict__ v_bias,
                     const float* __restrict__ logit_scale,
                     const float* __restrict__ proj_b,
                     float* __restrict__ out)
{
    extern __shared__ float sm[];
    float* sx     = sm + SX_OFF;
    float* sq     = sm + SQ_OFF;
    float* sk     = sm + SK_OFF;
    float* sv     = sm + SV_OFF;
    float* sinvq  = sm + SIQ_OFF;
    float* sinvk  = sm + SIK_OFF;
    float* sscale = sm + SSC_OFF;

    const int t = threadIdx.x;
    const int b = blockIdx.x;
    const int widx = b & (NW - 1);
    const float* xb = x + (size_t)b * NSEQ * CDIM;

    const int w    = t >> 5;
    const int lane = t & 31;
    const int g    = lane >> 2;
    const int qd   = lane & 3;

    // -------- load x window into smem (stride 196) --------
    for (int idx = t; idx < NSEQ * CDIM / 4; idx += NTHREADS) {
        float4 v4 = ((const float4*)xb)[idx];
        int n = (idx * 4) / CDIM;
        int k = (idx * 4) % CDIM;
        *(float4*)&sx[n * SXS + k] = v4;
    }
    if (t < NH) sscale[t] = __expf(fminf(logit_scale[t], 4.60517019f)); // ln(100)
    __syncthreads();

    // ================= Phase 1: QKV GEMM (64 x 576 x 192), 3xTF32 ==========
    {
        const int mg = w & 1;
        const int ng = w >> 1;
        const int cb = ng * 96;

        float acc[2][12][4];
        #pragma unroll
        for (int a = 0; a < 2; a++)
            #pragma unroll
            for (int nt = 0; nt < 12; nt++)
                #pragma unroll
                for (int e = 0; e < 4; e++) acc[a][nt][e] = 0.0f;

        for (int kc = 0; kc < 12; kc++) {
            #pragma unroll
            for (int kst = 0; kst < 2; kst++) {
                uint32_t ahi[2][4], alo[2][4];
                #pragma unroll
                for (int mt = 0; mt < 2; mt++) {
                    const float* xr = &sx[(mg * 32 + mt * 16 + g) * SXS + kc * 16 + kst * 8 + qd];
                    tfsplit(xr[0],           ahi[mt][0], alo[mt][0]);
                    tfsplit(xr[8 * SXS],     ahi[mt][1], alo[mt][1]);
                    tfsplit(xr[4],           ahi[mt][2], alo[mt][2]);
                    tfsplit(xr[8 * SXS + 4], ahi[mt][3], alo[mt][3]);
                }
                const uint4* wrow = &g_wq[(((ng * 12 + kc) * 2 + kst) * 12) * 32 + lane];
                #pragma unroll
                for (int nt = 0; nt < 12; nt++) {
                    uint4 bb = wrow[nt * 32];
                    #pragma unroll
                    for (int mt = 0; mt < 2; mt++) {
                        mma8(acc[mt][nt], ahi[mt], bb.x, bb.y);
                        mma8(acc[mt][nt], ahi[mt], bb.z, bb.w);
                        mma8(acc[mt][nt], alo[mt], bb.x, bb.y);
                    }
                }
            }
        }

        // scatter accumulators to sq / sk / sv; fold in row-norm partials
        const int s = ng >> 1;   // 0=q, 1=k, 2=v
        float ss[2][2][3];
        #pragma unroll
        for (int a = 0; a < 2; a++)
            #pragma unroll
            for (int c = 0; c < 2; c++)
                #pragma unroll
                for (int hh = 0; hh < 3; hh++) ss[a][c][hh] = 0.0f;

        #pragma unroll
        for (int mt = 0; mt < 2; mt++) {
            #pragma unroll
            for (int nt = 0; nt < 12; nt++) {
                int col0 = cb + nt * 8 + qd * 2;
                int rem = col0 - s * 192;
                int h = rem >> 5, d = rem & 31;
                int hs = nt >> 2;
                #pragma unroll
                for (int rr = 0; rr < 2; rr++) {
                    int n = mg * 32 + mt * 16 + g + rr * 8;
                    float v0 = acc[mt][nt][rr * 2 + 0];
                    float v1 = acc[mt][nt][rr * 2 + 1];
                    if (s == 0) {
                        v0 += q_bias[rem]; v1 += q_bias[rem + 1];
                        ss[mt][rr][hs] += v0 * v0 + v1 * v1;
                        sq[(h * 64 + n) * 33 + d]     = v0;
                        sq[(h * 64 + n) * 33 + d + 1] = v1;
                    } else if (s == 1) {
                        ss[mt][rr][hs] += v0 * v0 + v1 * v1;
                        sk[(h * 64 + n) * 33 + d]     = v0;
                        sk[(h * 64 + n) * 33 + d + 1] = v1;
                    } else {
                        sv[(h * 64 + n) * 33 + d]     = v0 + v_bias[rem];
                        sv[(h * 64 + n) * 33 + d + 1] = v1 + v_bias[rem + 1];
                    }
                }
            }
        }

        if (s < 2) {
            #pragma unroll
            for (int mt = 0; mt < 2; mt++)
                #pragma unroll
                for (int rr = 0; rr < 2; rr++)
                    #pragma unroll
                    for (int hs = 0; hs < 3; hs++) {
                        float tot = ss[mt][rr][hs];
                        tot += __shfl_xor_sync(0xffffffffu, tot, 1);
                        tot += __shfl_xor_sync(0xffffffffu, tot, 2);
                        if (qd == 0) {
                            int n = mg * 32 + mt * 16 + g + rr * 8;
                            int hh = (ng & 1) * 3 + hs;
                            float inv = 1.0f / fmaxf(sqrtf(tot), 1e-12f);
                            if (s == 0) sinvq[hh * 64 + n] = inv;
                            else        sinvk[hh * 64 + n] = inv;
                        }
                    }
        }
    }
    __syncthreads();

    // ============ Phase 2: attention via 3xTF32 mma (S, softmax, PV) =======
    {
        const int h  = w >> 1;
        const int m0 = (w & 1) * 32;

        float qsc[2][2], ksc[8];
        #pragma unroll
        for (int mt = 0; mt < 2; mt++) {
            qsc[mt][0] = sinvq[h * 64 + m0 + mt * 16 + g]     * sscale[h];
            qsc[mt][1] = sinvq[h * 64 + m0 + mt * 16 + g + 8] * sscale[h];
        }
        #pragma unroll
        for (int nt = 0; nt < 8; nt++) ksc[nt] = sinvk[h * 64 + nt * 8 + g];

        // ---- S = qn @ kn^T   (m=32, n=64, k=32) ----
        float p[2][8][4];
        #pragma unroll
        for (int mt = 0; mt < 2; mt++)
            #pragma unroll
            for (int nt = 0; nt < 8; nt++)
                #pragma unroll
                for (int e = 0; e < 4; e++) p[mt][nt][e] = 0.0f;

        #pragma unroll
        for (int kt = 0; kt < 4; kt++) {
            uint32_t ahi[2][4], alo[2][4];
            #pragma unroll
            for (int mt = 0; mt < 2; mt++) {
                const float* qr = &sq[(h * 64 + m0 + mt * 16 + g) * 33 + kt * 8 + qd];
                tfsplit(qr[0]          * qsc[mt][0], ahi[mt][0], alo[mt][0]);
                tfsplit(qr[8 * 33]     * qsc[mt][1], ahi[mt][1], alo[mt][1]);
                tfsplit(qr[4]          * qsc[mt][0], ahi[mt][2], alo[mt][2]);
                tfsplit(qr[8 * 33 + 4] * qsc[mt][1], ahi[mt][3], alo[mt][3]);
            }
            #pragma unroll
            for (int nt = 0; nt < 8; nt++) {
                const float* kr = &sk[(h * 64 + nt * 8 + g) * 33 + kt * 8 + qd];
                uint32_t bh0, bl0, bh1, bl1;
                tfsplit(kr[0] * ksc[nt], bh0, bl0);
                tfsplit(kr[4] * ksc[nt], bh1, bl1);
                #pragma unroll
                for (int mt = 0; mt < 2; mt++) {
                    mma8(p[mt][nt], ahi[mt], bh0, bh1);
                    mma8(p[mt][nt], ahi[mt], bl0, bl1);
                    mma8(p[mt][nt], alo[mt], bh0, bh1);
                }
            }
        }

        // ---- bias+mask, softmax over rows (row spread across qd group) ----
        const float* bmb = &g_bm[((size_t)widx * NH + h) * NSEQ * NSEQ];
        #pragma unroll
        for (int mt = 0; mt < 2; mt++) {
            #pragma unroll
            for (int r2 = 0; r2 < 2; r2++) {
                int row = m0 + mt * 16 + g + 8 * r2;
                const float* bmr = bmb + row * 64 + qd * 2;
                float mx = -1e30f;
                #pragma unroll
                for (int nt = 0; nt < 8; nt++) {
                    float2 bmv = *(const float2*)&bmr[nt * 8];
                    p[mt][nt][r2 * 2 + 0] += bmv.x;
                    p[mt][nt][r2 * 2 + 1] += bmv.y;
                    mx = fmaxf(mx, fmaxf(p[mt][nt][r2 * 2], p[mt][nt][r2 * 2 + 1]));
                }
                mx = fmaxf(mx, __shfl_xor_sync(0xffffffffu, mx, 1));
                mx = fmaxf(mx, __shfl_xor_sync(0xffffffffu, mx, 2));
                float sum = 0.0f;
                #pragma unroll
                for (int nt = 0; nt < 8; nt++) {
                    float e0 = __expf(p[mt][nt][r2 * 2 + 0] - mx);
                    float e1 = __expf(p[mt][nt][r2 * 2 + 1] - mx);
                    p[mt][nt][r2 * 2 + 0] = e0;
                    p[mt][nt][r2 * 2 + 1] = e1;
                    sum += e0 + e1;
                }
                sum += __shfl_xor_sync(0xffffffffu, sum, 1);
                sum += __shfl_xor_sync(0xffffffffu, sum, 2);
                float rs = 1.0f / sum;
                #pragma unroll
                for (int nt = 0; nt < 8; nt++) {
                    p[mt][nt][r2 * 2 + 0] *= rs;
                    p[mt][nt][r2 * 2 + 1] *= rs;
                }
            }
        }

        // ---- PV (m=32, n=32, k=64); P acc->A via intra-quad shfl ----
        float o[2][4][4];
        #pragma unroll
        for (int mt = 0; mt < 2; mt++)
            #pragma unroll
            for (int nt = 0; nt < 4; nt++)
                #pragma unroll
                for (int e = 0; e < 4; e++) o[mt][nt][e] = 0.0f;

        const int s0 = g * 4 + (qd >> 1);
        const int s1 = s0 + 2;
        const bool odd = (qd & 1);

        #pragma unroll
        for (int kt = 0; kt < 8; kt++) {
            uint32_t phi[2][4], plo[2][4];
            #pragma unroll
            for (int mt = 0; mt < 2; mt++) {
                float e0 = __shfl_sync(0xffffffffu, p[mt][kt][0], s0);
                float e1 = __shfl_sync(0xffffffffu, p[mt][kt][1], s0);
                float e2 = __shfl_sync(0xffffffffu, p[mt][kt][2], s0);
                float e3 = __shfl_sync(0xffffffffu, p[mt][kt][3], s0);
                float f0 = __shfl_sync(0xffffffffu, p[mt][kt][0], s1);
                float f1 = __shfl_sync(0xffffffffu, p[mt][kt][1], s1);
                float f2 = __shfl_sync(0xffffffffu, p[mt][kt][2], s1);
                float f3 = __shfl_sync(0xffffffffu, p[mt][kt][3], s1);
                float a0 = odd ? e1 : e0;
                float a1 = odd ? e3 : e2;
                float a2 = odd ? f1 : f0;
                float a3 = odd ? f3 : f2;
                tfsplit(a0, phi[mt][0], plo[mt][0]);
                tfsplit(a1, phi[mt][1], plo[mt][1]);
                tfsplit(a2, phi[mt][2], plo[mt][2]);
                tfsplit(a3, phi[mt][3], plo[mt][3]);
            }
            #pragma unroll
            for (int nt = 0; nt < 4; nt++) {
                float v0 = sv[(h * 64 + kt * 8 + qd) * 33     + nt * 8 + g];
                float v1 = sv[(h * 64 + kt * 8 + qd + 4) * 33 + nt * 8 + g];
                uint32_t vh0, vl0, vh1, vl1;
                tfsplit(v0, vh0, vl0);
                tfsplit(v1, vh1, vl1);
                #pragma unroll
                for (int mt = 0; mt < 2; mt++) {
                    mma8(o[mt][nt], phi[mt], vh0, vh1);
                    mma8(o[mt][nt], phi[mt], vl0, vl1);
                    mma8(o[mt][nt], plo[mt], vh0, vh1);
                }
            }
        }

        // ---- write attention output into sx [row][h*32+d] ----
        #pragma unroll
        for (int mt = 0; mt < 2; mt++) {
            #pragma unroll
            for (int nt = 0; nt < 4; nt++) {
                int col = h * 32 + nt * 8 + qd * 2;
                #pragma unroll
                for (int r2 = 0; r2 < 2; r2++) {
                    int row = m0 + mt * 16 + g + 8 * r2;
                    *(float2*)&sx[row * SXS + col] =
                        make_float2(o[mt][nt][r2 * 2 + 0], o[mt][nt][r2 * 2 + 1]);
                }
            }
        }
    }
    __syncthreads();

    // ================= Phase 3: proj GEMM (64 x 192 x 192), 3xTF32 ==========
    {
        const int mg = w & 1;
        const int ng = w >> 1;
        const int cb = ng * 32;

        float acc[2][4][4];
        #pragma unroll
        for (int a = 0; a < 2; a++)
            #pragma unroll
            for (int nt = 0; nt < 4; nt++)
                #pragma unroll
                for (int e = 0; e < 4; e++) acc[a][nt][e] = 0.0f;

        for (int kc = 0; kc < 12; kc++) {
            #pragma unroll
            for (int kst = 0; kst < 2; kst++) {
                uint32_t ahi[2][4], alo[2][4];
                #pragma unroll
                for (int mt = 0; mt < 2; mt++) {
                    const float* xr = &sx[(mg * 32 + mt * 16 + g) * SXS + kc * 16 + kst * 8 + qd];
                    tfsplit(xr[0],           ahi[mt][0], alo[mt][0]);
                    tfsplit(xr[8 * SXS],     ahi[mt][1], alo[mt][1]);
                    tfsplit(xr[4],           ahi[mt][2], alo[mt][2]);
                    tfsplit(xr[8 * SXS + 4], ahi[mt][3], alo[mt][3]);
                }
                const uint4* wrow = &g_wp[(((ng * 12 + kc) * 2 + kst) * 4) * 32 + lane];
                #pragma unroll
                for (int nt = 0; nt < 4; nt++) {
                    uint4 bb = wrow[nt * 32];
                    #pragma unroll
                    for (int mt = 0; mt < 2; mt++) {
                        mma8(acc[mt][nt], ahi[mt], bb.x, bb.y);
                        mma8(acc[mt][nt], ahi[mt], bb.z, bb.w);
                        mma8(acc[mt][nt], alo[mt], bb.x, bb.y);
                    }
                }
            }
        }

        float* ob = out + (size_t)b * NSEQ * CDIM;
        #pragma unroll
        for (int mt = 0; mt < 2; mt++) {
            #pragma unroll
            for (int nt = 0; nt < 4; nt++) {
                int col0 = cb + nt * 8 + qd * 2;
                float pb0 = proj_b[col0], pb1 = proj_b[col0 + 1];
                #pragma unroll
                for (int rr = 0; rr < 2; rr++) {
                    int n = mg * 32 + mt * 16 + g + rr * 8;
                    float2 o2 = make_float2(acc[mt][nt][rr * 2 + 0] + pb0,
                                            acc[mt][nt][rr * 2 + 1] + pb1);
                    *(float2*)&ob[n * 192 + col0] = o2;
                }
            }
        }
    }
}

// ---------------------------------------------------------------------------
extern "C" void kernel_launch(void* const* d_in, const int* in_sizes, int n_in,
                              void* d_out, int out_size)
{
    const float* x           = (const float*)d_in[0];
    const float* mask        = (const float*)d_in[1];
    const float* qkv_w       = (const float*)d_in[2];
    const float* q_bias      = (const float*)d_in[3];
    const float* v_bias      = (const float*)d_in[4];
    const float* logit_scale = (const float*)d_in[5];
    const float* cpb_w1      = (const float*)d_in[6];
    const float* cpb_b1      = (const float*)d_in[7];
    const float* cpb_w2      = (const float*)d_in[8];
    const float* proj_w      = (const float*)d_in[9];
    const float* proj_b      = (const float*)d_in[10];
    float* out = (float*)d_out;

    cudaFuncSetAttribute(win_attn_kernel,
                         cudaFuncAttributeMaxDynamicSharedMemorySize, SMEM_BYTES);

    prep_w_kernel<<<(QKV_FRAGS + PRJ_FRAGS + 255) / 256, 256>>>(qkv_w, proj_w);
    cpb_kernel<<<1, 256>>>(cpb_w1, cpb_b1, cpb_w2);
    bm_kernel<<<NW * NH, 256>>>(mask);
    win_attn_kernel<<<B_TOT, NTHREADS, SMEM_BYTES>>>(
        x, q_bias, v_bias, logit_scale, proj_b, out);
}

// round 6
// speedup vs baseline: 3.0542x; 1.1320x over previous
#include <cuda_runtime.h>
#include <math.h>
#include <stdint.h>

#define B_TOT   4096
#define NSEQ    64
#define CDIM    192
#define NH      6
#define NW      64
#define CPBH    512
#define NTHREADS 384

// Shared memory (floats):
//  sxh : 64*196  tf32-rounded x / attn-out (A-operand hi)
//  sal : 64*100  packed bf16 lo pairs (u32)
//  sq/sk/sv : 6*64*33 each (q,k pre-scaled by norms)
#define SXS 196
#define SLS 100
#define SXH_OFF 0
#define SAL_OFF (SXH_OFF + 64*SXS)
#define SQ_OFF  (SAL_OFF + 64*SLS)
#define SK_OFF  (SQ_OFF + NH*64*33)
#define SV_OFF  (SK_OFF + NH*64*33)
#define SSC_OFF (SV_OFF + NH*64*33)
#define SMEM_FLOATS (SSC_OFF + 8)
#define SMEM_BYTES (SMEM_FLOATS * 4)

__device__ float g_bias[NH * NSEQ * NSEQ];
__device__ float g_bm[(size_t)NW * NH * NSEQ * NSEQ];

// Weight tables: (ng, ks0..23, nt, lane) -> uint4(tf32 bh0, tf32 bh1, bf16x2 blo, bf16x2 bhi)
#define QKV_TBL (6*24*12*32)
#define PRJ_TBL (6*24*4*32)
__device__ uint4 g_wq[QKV_TBL];
__device__ uint4 g_wp[PRJ_TBL];

__device__ __forceinline__ uint32_t f2tf(float f) {
    uint32_t u; asm("cvt.rna.tf32.f32 %0, %1;" : "=r"(u) : "f"(f)); return u;
}
__device__ __forceinline__ float f2tff(float f) { return __uint_as_float(f2tf(f)); }
__device__ __forceinline__ uint32_t packbf(float hi, float lo) {
    uint32_t r; asm("cvt.rn.bf16x2.f32 %0, %1, %2;" : "=r"(r) : "f"(hi), "f"(lo)); return r;
}
__device__ __forceinline__ void mma8(float* d, const uint32_t* a, uint32_t b0, uint32_t b1) {
    asm volatile("mma.sync.aligned.m16n8k8.row.col.f32.tf32.tf32.f32 "
                 "{%0,%1,%2,%3},{%4,%5,%6,%7},{%8,%9},{%0,%1,%2,%3};"
                 : "+f"(d[0]), "+f"(d[1]), "+f"(d[2]), "+f"(d[3])
                 : "r"(a[0]), "r"(a[1]), "r"(a[2]), "r"(a[3]), "r"(b0), "r"(b1));
}
__device__ __forceinline__ void mma16bf(float* d, const uint32_t* a, uint32_t b0, uint32_t b1) {
    asm volatile("mma.sync.aligned.m16n8k16.row.col.f32.bf16.bf16.f32 "
                 "{%0,%1,%2,%3},{%4,%5,%6,%7},{%8,%9},{%0,%1,%2,%3};"
                 : "+f"(d[0]), "+f"(d[1]), "+f"(d[2]), "+f"(d[3])
                 : "r"(a[0]), "r"(a[1]), "r"(a[2]), "r"(a[3]), "r"(b0), "r"(b1));
}
__device__ __forceinline__ void tfsplit(float v, uint32_t& hi, uint32_t& lo) {
    hi = f2tf(v);
    lo = f2tf(v - __uint_as_float(hi));
}

// ---------------------------------------------------------------------------
__global__ void prep_w_kernel(const float* __restrict__ qkv_w,
                              const float* __restrict__ proj_w)
{
    int i = blockIdx.x * blockDim.x + threadIdx.x;
    const float* w; uint4* dst; int NT, idx;
    if (i < QKV_TBL)                { w = qkv_w;  dst = g_wq; NT = 12; idx = i; }
    else if (i < QKV_TBL + PRJ_TBL) { w = proj_w; dst = g_wp; NT = 4;  idx = i - QKV_TBL; }
    else return;

    int lane = idx & 31, r = idx >> 5;
    int nt = r % NT; r /= NT;
    int ks = r % 24; int ng = r / 24;
    int g = lane >> 2, qd = lane & 3;
    int col = ng * (NT * 8) + nt * 8 + g;
    const float* wr = &w[col * 192 + ks * 8];

    uint32_t bh0 = f2tf(wr[qd]);
    uint32_t bh1 = f2tf(wr[qd + 4]);
    float e0 = wr[2 * qd], e1 = wr[2 * qd + 1];
    uint32_t blo = packbf(e1 - f2tff(e1), e0 - f2tff(e0));
    uint32_t bhi = packbf(e1, e0);
    dst[idx] = make_uint4(bh0, bh1, blo, bhi);
}

// ---------------------------------------------------------------------------
__global__ void cpb_kernel(const float* __restrict__ w1,
                           const float* __restrict__ b1,
                           const float* __restrict__ w2)
{
    __shared__ float rpb[225 * NH];
    const int t = threadIdx.x;
    const float inv_log2_8 = 1.0f / 3.0f;

    for (int e = t; e < 225 * NH; e += 256) {
        int te = e / NH, h = e % NH;
        int i = te / 15, j = te % 15;
        float cy = (float)(i - 7) * (8.0f / 7.0f);
        float cx = (float)(j - 7) * (8.0f / 7.0f);
        cy = copysignf(log2f(fabsf(cy) + 1.0f), cy) * inv_log2_8;
        cx = copysignf(log2f(fabsf(cx) + 1.0f), cx) * inv_log2_8;
        float acc = 0.0f;
        for (int k = 0; k < CPBH; k++) {
            float hm = fmaxf(cy * w1[2 * k] + cx * w1[2 * k + 1] + b1[k], 0.0f);
            acc += hm * w2[h * CPBH + k];
        }
        rpb[te * NH + h] = acc;
    }
    __syncthreads();

    for (int e = t; e < NH * NSEQ * NSEQ; e += 256) {
        int h = e / (NSEQ * NSEQ);
        int rr = e % (NSEQ * NSEQ);
        int i = rr / NSEQ, j = rr % NSEQ;
        int dy = (i >> 3) - (j >> 3) + 7;
        int dx = (i & 7) - (j & 7) + 7;
        g_bias[e] = 16.0f / (1.0f + expf(-rpb[(dy * 15 + dx) * NH + h]));
    }
}

__global__ void bm_kernel(const float* __restrict__ mask)
{
    int blk = blockIdx.x;            // widx*NH + h
    int widx = blk / NH, h = blk % NH;
    const float* mrow = mask + (size_t)widx * NSEQ * NSEQ;
    const float* brow = g_bias + h * NSEQ * NSEQ;
    float* dst = g_bm + (size_t)blk * NSEQ * NSEQ;
    for (int i = threadIdx.x; i < NSEQ * NSEQ; i += 256)
        dst[i] = brow[i] + mrow[i];
}

// ---------------------------------------------------------------------------
__global__ __launch_bounds__(NTHREADS)
void win_attn_kernel(const float* __restrict__ x,
                     const float* __restrict__ q_bias,
                     const float* __restrict__ v_bias,
                     const float* __restrict__ logit_scale,
                     const float* __restrict__ proj_b,
                     float* __restrict__ out)
{
    extern __shared__ float sm[];
    float*    sxh = sm + SXH_OFF;
    uint32_t* sal = (uint32_t*)(sm + SAL_OFF);
    float*    sq  = sm + SQ_OFF;
    float*    sk  = sm + SK_OFF;
    float*    sv  = sm + SV_OFF;
    float*    sscale = sm + SSC_OFF;

    const int t = threadIdx.x;
    const int b = blockIdx.x;
    const int widx = b & (NW - 1);
    const float* xb = x + (size_t)b * NSEQ * CDIM;

    const int w    = t >> 5;
    const int lane = t & 31;
    const int g    = lane >> 2;
    const int qd   = lane & 3;

    // -------- load x: tf32-hi (f32) + packed bf16 lo --------
    for (int idx = t; idx < NSEQ * CDIM / 4; idx += NTHREADS) {
        float4 v4 = ((const float4*)xb)[idx];
        int n = (idx * 4) / CDIM;
        int k = (idx * 4) % CDIM;
        float h0 = f2tff(v4.x), h1 = f2tff(v4.y), h2 = f2tff(v4.z), h3 = f2tff(v4.w);
        *(float4*)&sxh[n * SXS + k] = make_float4(h0, h1, h2, h3);
        uint32_t u0 = packbf(v4.y - h1, v4.x - h0);
        uint32_t u1 = packbf(v4.w - h3, v4.z - h2);
        *(uint2*)&sal[n * SLS + (k >> 1)] = make_uint2(u0, u1);
    }
    if (t < NH) sscale[t] = __expf(fminf(logit_scale[t], 4.60517019f)); // ln(100)
    __syncthreads();

    // ============ Phase 1: QKV GEMM (tf32-hi + bf16-corr) ============
    {
        const int mg = w & 1;
        const int ng = w >> 1;

        float acc[2][12][4];
        #pragma unroll
        for (int a = 0; a < 2; a++)
            #pragma unroll
            for (int nt = 0; nt < 12; nt++)
                #pragma unroll
                for (int e = 0; e < 4; e++) acc[a][nt][e] = 0.0f;

        const uint4* wtab = &g_wq[(ng * 24 * 12) * 32 + lane];

        for (int ks = 0; ks < 24; ks++) {
            int k0 = ks * 8;
            uint32_t ah[2][4], ac[2][4];
            #pragma unroll
            for (int mt = 0; mt < 2; mt++) {
                int r0 = mg * 32 + mt * 16 + g;
                const float* X0 = &sxh[r0 * SXS + k0];
                const float* X8 = X0 + 8 * SXS;
                ah[mt][0] = __float_as_uint(X0[qd]);
                ah[mt][1] = __float_as_uint(X8[qd]);
                ah[mt][2] = __float_as_uint(X0[qd + 4]);
                ah[mt][3] = __float_as_uint(X8[qd + 4]);
                float2 p0 = *(const float2*)&X0[2 * qd];
                float2 p8 = *(const float2*)&X8[2 * qd];
                ac[mt][0] = packbf(p0.y, p0.x);
                ac[mt][1] = packbf(p8.y, p8.x);
                ac[mt][2] = sal[r0 * SLS + (k0 >> 1) + qd];
                ac[mt][3] = sal[(r0 + 8) * SLS + (k0 >> 1) + qd];
            }
            const uint4* wrow = wtab + (ks * 12) * 32;
            #pragma unroll
            for (int nt = 0; nt < 12; nt++) {
                uint4 bb = wrow[nt * 32];
                #pragma unroll
                for (int mt = 0; mt < 2; mt++) {
                    mma8(acc[mt][nt], ah[mt], bb.x, bb.y);
                    mma16bf(acc[mt][nt], ac[mt], bb.z, bb.w);
                }
            }
        }

        // ---- norms (q,k) then scatter with folded scales ----
        const int s = ng >> 1;   // 0=q, 1=k, 2=v
        float inv[2][2][3];
        if (s < 2) {
            float ssq[2][2][3];
            #pragma unroll
            for (int a = 0; a < 2; a++)
                #pragma unroll
                for (int c = 0; c < 2; c++)
                    #pragma unroll
                    for (int hh = 0; hh < 3; hh++) ssq[a][c][hh] = 0.0f;
            #pragma unroll
            for (int mt = 0; mt < 2; mt++)
                #pragma unroll
                for (int nt = 0; nt < 12; nt++) {
                    int rem = ng * 96 + nt * 8 + qd * 2 - s * 192;
                    #pragma unroll
                    for (int rr = 0; rr < 2; rr++) {
                        float v0 = acc[mt][nt][rr * 2 + 0];
                        float v1 = acc[mt][nt][rr * 2 + 1];
                        if (s == 0) { v0 += q_bias[rem]; v1 += q_bias[rem + 1]; }
                        ssq[mt][rr][nt >> 2] += v0 * v0 + v1 * v1;
                    }
                }
            #pragma unroll
            for (int mt = 0; mt < 2; mt++)
                #pragma unroll
                for (int rr = 0; rr < 2; rr++)
                    #pragma unroll
                    for (int hs = 0; hs < 3; hs++) {
                        float tot = ssq[mt][rr][hs];
                        tot += __shfl_xor_sync(0xffffffffu, tot, 1);
                        tot += __shfl_xor_sync(0xffffffffu, tot, 2);
                        float sc = (s == 0) ? sscale[(ng & 1) * 3 + hs] : 1.0f;
                        inv[mt][rr][hs] = sc / fmaxf(sqrtf(tot), 1e-12f);
                    }
        }

        #pragma unroll
        for (int mt = 0; mt < 2; mt++) {
            #pragma unroll
            for (int nt = 0; nt < 12; nt++) {
                int rem = ng * 96 + nt * 8 + qd * 2 - s * 192;
                int h = rem >> 5, d = rem & 31;
                #pragma unroll
                for (int rr = 0; rr < 2; rr++) {
                    int n = mg * 32 + mt * 16 + g + rr * 8;
                    float v0 = acc[mt][nt][rr * 2 + 0];
                    float v1 = acc[mt][nt][rr * 2 + 1];
                    if (s == 0) {
                        float iv = inv[mt][rr][nt >> 2];
                        sq[(h * 64 + n) * 33 + d]     = (v0 + q_bias[rem]) * iv;
                        sq[(h * 64 + n) * 33 + d + 1] = (v1 + q_bias[rem + 1]) * iv;
                    } else if (s == 1) {
                        float iv = inv[mt][rr][nt >> 2];
                        sk[(h * 64 + n) * 33 + d]     = v0 * iv;
                        sk[(h * 64 + n) * 33 + d + 1] = v1 * iv;
                    } else {
                        sv[(h * 64 + n) * 33 + d]     = v0 + v_bias[rem];
                        sv[(h * 64 + n) * 33 + d + 1] = v1 + v_bias[rem + 1];
                    }
                }
            }
        }
    }
    __syncthreads();

    // ============ Phase 2: attention (3xTF32 S and PV) ============
    {
        const int h  = w >> 1;
        const int m0 = (w & 1) * 32;

        float p[2][8][4];
        #pragma unroll
        for (int mt = 0; mt < 2; mt++)
            #pragma unroll
            for (int nt = 0; nt < 8; nt++)
                #pragma unroll
                for (int e = 0; e < 4; e++) p[mt][nt][e] = 0.0f;

        #pragma unroll
        for (int kt = 0; kt < 4; kt++) {
            uint32_t ahi[2][4], alo[2][4];
            #pragma unroll
            for (int mt = 0; mt < 2; mt++) {
                const float* qr = &sq[(h * 64 + m0 + mt * 16 + g) * 33 + kt * 8 + qd];
                tfsplit(qr[0],          ahi[mt][0], alo[mt][0]);
                tfsplit(qr[8 * 33],     ahi[mt][1], alo[mt][1]);
                tfsplit(qr[4],          ahi[mt][2], alo[mt][2]);
                tfsplit(qr[8 * 33 + 4], ahi[mt][3], alo[mt][3]);
            }
            #pragma unroll
            for (int nt = 0; nt < 8; nt++) {
                const float* kr = &sk[(h * 64 + nt * 8 + g) * 33 + kt * 8 + qd];
                uint32_t bh0, bl0, bh1, bl1;
                tfsplit(kr[0], bh0, bl0);
                tfsplit(kr[4], bh1, bl1);
                #pragma unroll
                for (int mt = 0; mt < 2; mt++) {
                    mma8(p[mt][nt], ahi[mt], bh0, bh1);
                    mma8(p[mt][nt], ahi[mt], bl0, bl1);
                    mma8(p[mt][nt], alo[mt], bh0, bh1);
                }
            }
        }

        // ---- bias+mask, softmax ----
        const float* bmb = &g_bm[((size_t)widx * NH + h) * NSEQ * NSEQ];
        #pragma unroll
        for (int mt = 0; mt < 2; mt++) {
            #pragma unroll
            for (int r2 = 0; r2 < 2; r2++) {
                int row = m0 + mt * 16 + g + 8 * r2;
                const float* bmr = bmb + row * 64 + qd * 2;
                float mx = -1e30f;
                #pragma unroll
                for (int nt = 0; nt < 8; nt++) {
                    float2 bmv = *(const float2*)&bmr[nt * 8];
                    p[mt][nt][r2 * 2 + 0] += bmv.x;
                    p[mt][nt][r2 * 2 + 1] += bmv.y;
                    mx = fmaxf(mx, fmaxf(p[mt][nt][r2 * 2], p[mt][nt][r2 * 2 + 1]));
                }
                mx = fmaxf(mx, __shfl_xor_sync(0xffffffffu, mx, 1));
                mx = fmaxf(mx, __shfl_xor_sync(0xffffffffu, mx, 2));
                float sum = 0.0f;
                #pragma unroll
                for (int nt = 0; nt < 8; nt++) {
                    float e0 = __expf(p[mt][nt][r2 * 2 + 0] - mx);
                    float e1 = __expf(p[mt][nt][r2 * 2 + 1] - mx);
                    p[mt][nt][r2 * 2 + 0] = e0;
                    p[mt][nt][r2 * 2 + 1] = e1;
                    sum += e0 + e1;
                }
                sum += __shfl_xor_sync(0xffffffffu, sum, 1);
                sum += __shfl_xor_sync(0xffffffffu, sum, 2);
                float rs = 1.0f / sum;
                #pragma unroll
                for (int nt = 0; nt < 8; nt++) {
                    p[mt][nt][r2 * 2 + 0] *= rs;
                    p[mt][nt][r2 * 2 + 1] *= rs;
                }
            }
        }

        // ---- PV ----
        float o[2][4][4];
        #pragma unroll
        for (int mt = 0; mt < 2; mt++)
            #pragma unroll
            for (int nt = 0; nt < 4; nt++)
                #pragma unroll
                for (int e = 0; e < 4; e++) o[mt][nt][e] = 0.0f;

        const int s0 = g * 4 + (qd >> 1);
        const int s1 = s0 + 2;
        const bool odd = (qd & 1);

        #pragma unroll
        for (int kt = 0; kt < 8; kt++) {
            uint32_t phi[2][4], plo[2][4];
            #pragma unroll
            for (int mt = 0; mt < 2; mt++) {
                float e0 = __shfl_sync(0xffffffffu, p[mt][kt][0], s0);
                float e1 = __shfl_sync(0xffffffffu, p[mt][kt][1], s0);
                float e2 = __shfl_sync(0xffffffffu, p[mt][kt][2], s0);
                float e3 = __shfl_sync(0xffffffffu, p[mt][kt][3], s0);
                float f0 = __shfl_sync(0xffffffffu, p[mt][kt][0], s1);
                float f1 = __shfl_sync(0xffffffffu, p[mt][kt][1], s1);
                float f2 = __shfl_sync(0xffffffffu, p[mt][kt][2], s1);
                float f3 = __shfl_sync(0xffffffffu, p[mt][kt][3], s1);
                tfsplit(odd ? e1 : e0, phi[mt][0], plo[mt][0]);
                tfsplit(odd ? e3 : e2, phi[mt][1], plo[mt][1]);
                tfsplit(odd ? f1 : f0, phi[mt][2], plo[mt][2]);
                tfsplit(odd ? f3 : f2, phi[mt][3], plo[mt][3]);
            }
            #pragma unroll
            for (int nt = 0; nt < 4; nt++) {
                float v0 = sv[(h * 64 + kt * 8 + qd) * 33     + nt * 8 + g];
                float v1 = sv[(h * 64 + kt * 8 + qd + 4) * 33 + nt * 8 + g];
                uint32_t vh0, vl0, vh1, vl1;
                tfsplit(v0, vh0, vl0);
                tfsplit(v1, vh1, vl1);
                #pragma unroll
                for (int mt = 0; mt < 2; mt++) {
                    mma8(o[mt][nt], phi[mt], vh0, vh1);
                    mma8(o[mt][nt], phi[mt], vl0, vl1);
                    mma8(o[mt][nt], plo[mt], vh0, vh1);
                }
            }
        }

        // ---- write attn output as hi + packed lo ----
        #pragma unroll
        for (int mt = 0; mt < 2; mt++) {
            #pragma unroll
            for (int nt = 0; nt < 4; nt++) {
                int col0 = h * 32 + nt * 8 + qd * 2;
                #pragma unroll
                for (int r2 = 0; r2 < 2; r2++) {
                    int row = m0 + mt * 16 + g + 8 * r2;
                    float o0 = o[mt][nt][r2 * 2 + 0];
                    float o1 = o[mt][nt][r2 * 2 + 1];
                    float h0 = f2tff(o0), h1 = f2tff(o1);
                    *(float2*)&sxh[row * SXS + col0] = make_float2(h0, h1);
                    sal[row * SLS + (col0 >> 1)] = packbf(o1 - h1, o0 - h0);
                }
            }
        }
    }
    __syncthreads();

    // ============ Phase 3: proj GEMM (tf32-hi + bf16-corr) ============
    {
        const int mg = w & 1;
        const int ng = w >> 1;

        float acc[2][4][4];
        #pragma unroll
        for (int a = 0; a < 2; a++)
            #pragma unroll
            for (int nt = 0; nt < 4; nt++)
                #pragma unroll
                for (int e = 0; e < 4; e++) acc[a][nt][e] = 0.0f;

        const uint4* wtab = &g_wp[(ng * 24 * 4) * 32 + lane];

        for (int ks = 0; ks < 24; ks++) {
            int k0 = ks * 8;
            uint32_t ah[2][4], ac[2][4];
            #pragma unroll
            for (int mt = 0; mt < 2; mt++) {
                int r0 = mg * 32 + mt * 16 + g;
                const float* X0 = &sxh[r0 * SXS + k0];
                const float* X8 = X0 + 8 * SXS;
                ah[mt][0] = __float_as_uint(X0[qd]);
                ah[mt][1] = __float_as_uint(X8[qd]);
                ah[mt][2] = __float_as_uint(X0[qd + 4]);
                ah[mt][3] = __float_as_uint(X8[qd + 4]);
                float2 p0 = *(const float2*)&X0[2 * qd];
                float2 p8 = *(const float2*)&X8[2 * qd];
                ac[mt][0] = packbf(p0.y, p0.x);
                ac[mt][1] = packbf(p8.y, p8.x);
                ac[mt][2] = sal[r0 * SLS + (k0 >> 1) + qd];
                ac[mt][3] = sal[(r0 + 8) * SLS + (k0 >> 1) + qd];
            }
            const uint4* wrow = wtab + (ks * 4) * 32;
            #pragma unroll
            for (int nt = 0; nt < 4; nt++) {
                uint4 bb = wrow[nt * 32];
                #pragma unroll
                for (int mt = 0; mt < 2; mt++) {
                    mma8(acc[mt][nt], ah[mt], bb.x, bb.y);
                    mma16bf(acc[mt][nt], ac[mt], bb.z, bb.w);
                }
            }
        }

        float* ob = out + (size_t)b * NSEQ * CDIM;
        #pragma unroll
        for (int mt = 0; mt < 2; mt++) {
            #pragma unroll
            for (int nt = 0; nt < 4; nt++) {
                int col0 = ng * 32 + nt * 8 + qd * 2;
                float pb0 = proj_b[col0], pb1 = proj_b[col0 + 1];
                #pragma unroll
                for (int rr = 0; rr < 2; rr++) {
                    int n = mg * 32 + mt * 16 + g + rr * 8;
                    *(float2*)&ob[n * 192 + col0] =
                        make_float2(acc[mt][nt][rr * 2 + 0] + pb0,
                                    acc[mt][nt][rr * 2 + 1] + pb1);
                }
            }
        }
    }
}

// ---------------------------------------------------------------------------
extern "C" void kernel_launch(void* const* d_in, const int* in_sizes, int n_in,
                              void* d_out, int out_size)
{
    const float* x           = (const float*)d_in[0];
    const float* mask        = (const float*)d_in[1];
    const float* qkv_w       = (const float*)d_in[2];
    const float* q_bias      = (const float*)d_in[3];
    const float* v_bias      = (const float*)d_in[4];
    const float* logit_scale = (const float*)d_in[5];
    const float* cpb_w1      = (const float*)d_in[6];
    const float* cpb_b1      = (const float*)d_in[7];
    const float* cpb_w2      = (const float*)d_in[8];
    const float* proj_w      = (const float*)d_in[9];
    const float* proj_b      = (const float*)d_in[10];
    float* out = (float*)d_out;

    cudaFuncSetAttribute(win_attn_kernel,
                         cudaFuncAttributeMaxDynamicSharedMemorySize, SMEM_BYTES);

    prep_w_kernel<<<(QKV_TBL + PRJ_TBL + 255) / 256, 256>>>(qkv_w, proj_w);
    cpb_kernel<<<1, 256>>>(cpb_w1, cpb_b1, cpb_w2);
    bm_kernel<<<NW * NH, 256>>>(mask);
    win_attn_kernel<<<B_TOT, NTHREADS, SMEM_BYTES>>>(
        x, q_bias, v_bias, logit_scale, proj_b, out);
}

// round 7
// speedup vs baseline: 3.2886x; 1.0767x over previous
#include <cuda_runtime.h>
#include <math.h>
#include <stdint.h>

#define B_TOT   4096
#define NSEQ    64
#define CDIM    192
#define NH      6
#define NW      64
#define CPBH    512
#define NTHREADS 384

// Shared memory (floats), all XOR-swizzled, no padding:
//  sxh : 64*192 tf32-rounded x / attn-out, col ^ ((row&7)<<2)
//  sal : 64*96  packed bf16-lo pairs (u32), pairidx ^ ((row&7)<<2)
//  sq/sk : 6*64*32, col ^ ((row&7)<<2)   (pre-scaled by norms)
//  sv    : 6*64*32, col ^ ((row&3)<<3)
#define SXS 192
#define SLS 96
#define SXH_OFF 0
#define SAL_OFF (SXH_OFF + 64*SXS)
#define SQ_OFF  (SAL_OFF + 64*SLS)
#define SK_OFF  (SQ_OFF + NH*64*32)
#define SV_OFF  (SK_OFF + NH*64*32)
#define SSC_OFF (SV_OFF + NH*64*32)
#define SMEM_FLOATS (SSC_OFF + 8)
#define SMEM_BYTES (SMEM_FLOATS * 4)

__device__ float g_bias[NH * NSEQ * NSEQ];
__device__ float g_bm[(size_t)NW * NH * NSEQ * NSEQ];

// Weight tables: (ng, ks, nt, lane) -> uint4(tf32 bh0, tf32 bh1, bf16x2 blo, bf16x2 bhi)
#define QKV_TBL (6*24*12*32)
#define PRJ_TBL (6*24*4*32)
__device__ uint4 g_wq[QKV_TBL];
__device__ uint4 g_wp[PRJ_TBL];

__device__ __forceinline__ uint32_t f2tf(float f) {
    uint32_t u; asm("cvt.rna.tf32.f32 %0, %1;" : "=r"(u) : "f"(f)); return u;
}
__device__ __forceinline__ float f2tff(float f) { return __uint_as_float(f2tf(f)); }
__device__ __forceinline__ uint32_t packbf(float hi, float lo) {
    uint32_t r; asm("cvt.rn.bf16x2.f32 %0, %1, %2;" : "=r"(r) : "f"(hi), "f"(lo)); return r;
}
__device__ __forceinline__ void mma8(float* d, const uint32_t* a, uint32_t b0, uint32_t b1) {
    asm volatile("mma.sync.aligned.m16n8k8.row.col.f32.tf32.tf32.f32 "
                 "{%0,%1,%2,%3},{%4,%5,%6,%7},{%8,%9},{%0,%1,%2,%3};"
                 : "+f"(d[0]), "+f"(d[1]), "+f"(d[2]), "+f"(d[3])
                 : "r"(a[0]), "r"(a[1]), "r"(a[2]), "r"(a[3]), "r"(b0), "r"(b1));
}
__device__ __forceinline__ void mma16bf(float* d, const uint32_t* a, uint32_t b0, uint32_t b1) {
    asm volatile("mma.sync.aligned.m16n8k16.row.col.f32.bf16.bf16.f32 "
                 "{%0,%1,%2,%3},{%4,%5,%6,%7},{%8,%9},{%0,%1,%2,%3};"
                 : "+f"(d[0]), "+f"(d[1]), "+f"(d[2]), "+f"(d[3])
                 : "r"(a[0]), "r"(a[1]), "r"(a[2]), "r"(a[3]), "r"(b0), "r"(b1));
}
__device__ __forceinline__ void tfsplit(float v, uint32_t& hi, uint32_t& lo) {
    hi = f2tf(v);
    lo = f2tf(v - __uint_as_float(hi));
}

// ---------------------------------------------------------------------------
__global__ void prep_w_kernel(const float* __restrict__ qkv_w,
                              const float* __restrict__ proj_w)
{
    int i = blockIdx.x * blockDim.x + threadIdx.x;
    const float* w; uint4* dst; int NT, idx;
    if (i < QKV_TBL)                { w = qkv_w;  dst = g_wq; NT = 12; idx = i; }
    else if (i < QKV_TBL + PRJ_TBL) { w = proj_w; dst = g_wp; NT = 4;  idx = i - QKV_TBL; }
    else return;

    int lane = idx & 31, r = idx >> 5;
    int nt = r % NT; r /= NT;
    int ks = r % 24; int ng = r / 24;
    int g = lane >> 2, qd = lane & 3;
    int col = ng * (NT * 8) + nt * 8 + g;
    const float* wr = &w[col * 192 + ks * 8];

    uint32_t bh0 = f2tf(wr[qd]);
    uint32_t bh1 = f2tf(wr[qd + 4]);
    float e0 = wr[2 * qd], e1 = wr[2 * qd + 1];
    uint32_t blo = packbf(e1 - f2tff(e1), e0 - f2tff(e0));
    uint32_t bhi = packbf(e1, e0);
    dst[idx] = make_uint4(bh0, bh1, blo, bhi);
}

// ---------------------------------------------------------------------------
__global__ void cpb_kernel(const float* __restrict__ w1,
                           const float* __restrict__ b1,
                           const float* __restrict__ w2)
{
    __shared__ float rpb[225 * NH];
    const int t = threadIdx.x;
    const float inv_log2_8 = 1.0f / 3.0f;

    for (int e = t; e < 225 * NH; e += 256) {
        int te = e / NH, h = e % NH;
        int i = te / 15, j = te % 15;
        float cy = (float)(i - 7) * (8.0f / 7.0f);
        float cx = (float)(j - 7) * (8.0f / 7.0f);
        cy = copysignf(log2f(fabsf(cy) + 1.0f), cy) * inv_log2_8;
        cx = copysignf(log2f(fabsf(cx) + 1.0f), cx) * inv_log2_8;
        float acc = 0.0f;
        for (int k = 0; k < CPBH; k++) {
            float hm = fmaxf(cy * w1[2 * k] + cx * w1[2 * k + 1] + b1[k], 0.0f);
            acc += hm * w2[h * CPBH + k];
        }
        rpb[te * NH + h] = acc;
    }
    __syncthreads();

    for (int e = t; e < NH * NSEQ * NSEQ; e += 256) {
        int h = e / (NSEQ * NSEQ);
        int rr = e % (NSEQ * NSEQ);
        int i = rr / NSEQ, j = rr % NSEQ;
        int dy = (i >> 3) - (j >> 3) + 7;
        int dx = (i & 7) - (j & 7) + 7;
        g_bias[e] = 16.0f / (1.0f + expf(-rpb[(dy * 15 + dx) * NH + h]));
    }
}

__global__ void bm_kernel(const float* __restrict__ mask)
{
    int blk = blockIdx.x;            // widx*NH + h
    int widx = blk / NH, h = blk % NH;
    const float* mrow = mask + (size_t)widx * NSEQ * NSEQ;
    const float* brow = g_bias + h * NSEQ * NSEQ;
    float* dst = g_bm + (size_t)blk * NSEQ * NSEQ;
    for (int i = threadIdx.x; i < NSEQ * NSEQ; i += 256)
        dst[i] = brow[i] + mrow[i];
}

// ---------------------------------------------------------------------------
__global__ __launch_bounds__(NTHREADS)
void win_attn_kernel(const float* __restrict__ x,
                     const float* __restrict__ q_bias,
                     const float* __restrict__ v_bias,
                     const float* __restrict__ logit_scale,
                     const float* __restrict__ proj_b,
                     float* __restrict__ out)
{
    extern __shared__ float sm[];
    float*    sxh = sm + SXH_OFF;
    uint32_t* sal = (uint32_t*)(sm + SAL_OFF);
    float*    sq  = sm + SQ_OFF;
    float*    sk  = sm + SK_OFF;
    float*    sv  = sm + SV_OFF;
    float*    sscale = sm + SSC_OFF;

    const int t = threadIdx.x;
    const int b = blockIdx.x;
    const int widx = b & (NW - 1);
    const float* xb = x + (size_t)b * NSEQ * CDIM;

    const int w    = t >> 5;
    const int lane = t & 31;
    const int g    = lane >> 2;
    const int qd   = lane & 3;
    const int swg  = g << 2;          // row-based swizzle for fragment rows

    // -------- load x: tf32-hi (f32, swizzled) + packed bf16 lo --------
    for (int idx = t; idx < NSEQ * CDIM / 4; idx += NTHREADS) {
        float4 v4 = ((const float4*)xb)[idx];
        int n = (idx * 4) / CDIM;
        int k = (idx * 4) % CDIM;
        int sw = (n & 7) << 2;
        float h0 = f2tff(v4.x), h1 = f2tff(v4.y), h2 = f2tff(v4.z), h3 = f2tff(v4.w);
        *(float4*)&sxh[n * SXS + (k ^ sw)] = make_float4(h0, h1, h2, h3);
        uint32_t u0 = packbf(v4.y - h1, v4.x - h0);
        uint32_t u1 = packbf(v4.w - h3, v4.z - h2);
        *(uint2*)&sal[n * SLS + ((k >> 1) ^ sw)] = make_uint2(u0, u1);
    }
    if (t < NH) sscale[t] = __expf(fminf(logit_scale[t], 4.60517019f)); // ln(100)
    __syncthreads();

    // ============ Phase 1: QKV GEMM (tf32-hi + bf16-corr) ============
    {
        const int mg = w & 1;
        const int ng = w >> 1;

        float acc[2][12][4];
        #pragma unroll
        for (int a = 0; a < 2; a++)
            #pragma unroll
            for (int nt = 0; nt < 12; nt++)
                #pragma unroll
                for (int e = 0; e < 4; e++) acc[a][nt][e] = 0.0f;

        const uint4* wtab = &g_wq[(ng * 24 * 12) * 32 + lane];

        for (int ks = 0; ks < 24; ks++) {
            int k0 = ks * 8;
            uint32_t ah[2][4], ac[2][4];
            #pragma unroll
            for (int mt = 0; mt < 2; mt++) {
                int r0 = mg * 32 + mt * 16 + g;
                const float* X0 = &sxh[r0 * SXS];
                const float* X8 = X0 + 8 * SXS;
                int cA = (k0 + qd) ^ swg, cB = (k0 + qd + 4) ^ swg;
                ah[mt][0] = __float_as_uint(X0[cA]);
                ah[mt][1] = __float_as_uint(X8[cA]);
                ah[mt][2] = __float_as_uint(X0[cB]);
                ah[mt][3] = __float_as_uint(X8[cB]);
                int cC = (k0 + 2 * qd) ^ swg;
                float2 p0 = *(const float2*)&X0[cC];
                float2 p8 = *(const float2*)&X8[cC];
                ac[mt][0] = packbf(p0.y, p0.x);
                ac[mt][1] = packbf(p8.y, p8.x);
                int cU = ((k0 >> 1) + qd) ^ swg;
                ac[mt][2] = sal[r0 * SLS + cU];
                ac[mt][3] = sal[(r0 + 8) * SLS + cU];
            }
            const uint4* wrow = wtab + (ks * 12) * 32;
            #pragma unroll
            for (int nt = 0; nt < 12; nt++) {
                uint4 bb = wrow[nt * 32];
                #pragma unroll
                for (int mt = 0; mt < 2; mt++) {
                    mma8(acc[mt][nt], ah[mt], bb.x, bb.y);
                    mma16bf(acc[mt][nt], ac[mt], bb.z, bb.w);
                }
            }
        }

        // ---- norms (q,k) then scatter with folded scales ----
        const int s = ng >> 1;   // 0=q, 1=k, 2=v
        float inv[2][2][3];
        if (s < 2) {
            float ssq[2][2][3];
            #pragma unroll
            for (int a = 0; a < 2; a++)
                #pragma unroll
                for (int c = 0; c < 2; c++)
                    #pragma unroll
                    for (int hh = 0; hh < 3; hh++) ssq[a][c][hh] = 0.0f;
            #pragma unroll
            for (int mt = 0; mt < 2; mt++)
                #pragma unroll
                for (int nt = 0; nt < 12; nt++) {
                    int rem = ng * 96 + nt * 8 + qd * 2 - s * 192;
                    #pragma unroll
                    for (int rr = 0; rr < 2; rr++) {
                        float v0 = acc[mt][nt][rr * 2 + 0];
                        float v1 = acc[mt][nt][rr * 2 + 1];
                        if (s == 0) { v0 += q_bias[rem]; v1 += q_bias[rem + 1]; }
                        ssq[mt][rr][nt >> 2] += v0 * v0 + v1 * v1;
                    }
                }
            #pragma unroll
            for (int mt = 0; mt < 2; mt++)
                #pragma unroll
                for (int rr = 0; rr < 2; rr++)
                    #pragma unroll
                    for (int hs = 0; hs < 3; hs++) {
                        float tot = ssq[mt][rr][hs];
                        tot += __shfl_xor_sync(0xffffffffu, tot, 1);
                        tot += __shfl_xor_sync(0xffffffffu, tot, 2);
                        float sc = (s == 0) ? sscale[(ng & 1) * 3 + hs] : 1.0f;
                        inv[mt][rr][hs] = sc / fmaxf(sqrtf(tot), 1e-12f);
                    }
        }

        #pragma unroll
        for (int mt = 0; mt < 2; mt++) {
            #pragma unroll
            for (int nt = 0; nt < 12; nt++) {
                int rem = ng * 96 + nt * 8 + qd * 2 - s * 192;
                int h = rem >> 5, d = rem & 31;
                #pragma unroll
                for (int rr = 0; rr < 2; rr++) {
                    int n = mg * 32 + mt * 16 + g + rr * 8;
                    float v0 = acc[mt][nt][rr * 2 + 0];
                    float v1 = acc[mt][nt][rr * 2 + 1];
                    if (s == 0) {
                        float iv = inv[mt][rr][nt >> 2];
                        *(float2*)&sq[(h * 64 + n) * 32 + (d ^ swg)] =
                            make_float2((v0 + q_bias[rem]) * iv, (v1 + q_bias[rem + 1]) * iv);
                    } else if (s == 1) {
                        float iv = inv[mt][rr][nt >> 2];
                        *(float2*)&sk[(h * 64 + n) * 32 + (d ^ swg)] =
                            make_float2(v0 * iv, v1 * iv);
                    } else {
                        *(float2*)&sv[(h * 64 + n) * 32 + (d ^ ((g & 3) << 3))] =
                            make_float2(v0 + v_bias[rem], v1 + v_bias[rem + 1]);
                    }
                }
            }
        }
    }
    __syncthreads();

    // ============ Phase 2: attention (3xTF32 S and PV) ============
    {
        const int h  = w >> 1;
        const int m0 = (w & 1) * 32;

        float p[2][8][4];
        #pragma unroll
        for (int mt = 0; mt < 2; mt++)
            #pragma unroll
            for (int nt = 0; nt < 8; nt++)
                #pragma unroll
                for (int e = 0; e < 4; e++) p[mt][nt][e] = 0.0f;

        #pragma unroll
        for (int kt = 0; kt < 4; kt++) {
            int cA = (kt * 8 + qd) ^ swg, cB = (kt * 8 + qd + 4) ^ swg;
            uint32_t ahi[2][4], alo[2][4];
            #pragma unroll
            for (int mt = 0; mt < 2; mt++) {
                const float* Q0 = &sq[(h * 64 + m0 + mt * 16 + g) * 32];
                const float* Q8 = Q0 + 8 * 32;
                tfsplit(Q0[cA], ahi[mt][0], alo[mt][0]);
                tfsplit(Q8[cA], ahi[mt][1], alo[mt][1]);
                tfsplit(Q0[cB], ahi[mt][2], alo[mt][2]);
                tfsplit(Q8[cB], ahi[mt][3], alo[mt][3]);
            }
            #pragma unroll
            for (int nt = 0; nt < 8; nt++) {
                const float* K0 = &sk[(h * 64 + nt * 8 + g) * 32];
                uint32_t bh0, bl0, bh1, bl1;
                tfsplit(K0[cA], bh0, bl0);
                tfsplit(K0[cB], bh1, bl1);
                #pragma unroll
                for (int mt = 0; mt < 2; mt++) {
                    mma8(p[mt][nt], ahi[mt], bh0, bh1);
                    mma8(p[mt][nt], ahi[mt], bl0, bl1);
                    mma8(p[mt][nt], alo[mt], bh0, bh1);
                }
            }
        }

        // ---- bias+mask, softmax ----
        const float* bmb = &g_bm[((size_t)widx * NH + h) * NSEQ * NSEQ];
        #pragma unroll
        for (int mt = 0; mt < 2; mt++) {
            #pragma unroll
            for (int r2 = 0; r2 < 2; r2++) {
                int row = m0 + mt * 16 + g + 8 * r2;
                const float* bmr = bmb + row * 64 + qd * 2;
                float mx = -1e30f;
                #pragma unroll
                for (int nt = 0; nt < 8; nt++) {
                    float2 bmv = *(const float2*)&bmr[nt * 8];
                    p[mt][nt][r2 * 2 + 0] += bmv.x;
                    p[mt][nt][r2 * 2 + 1] += bmv.y;
                    mx = fmaxf(mx, fmaxf(p[mt][nt][r2 * 2], p[mt][nt][r2 * 2 + 1]));
                }
                mx = fmaxf(mx, __shfl_xor_sync(0xffffffffu, mx, 1));
                mx = fmaxf(mx, __shfl_xor_sync(0xffffffffu, mx, 2));
                float sum = 0.0f;
                #pragma unroll
                for (int nt = 0; nt < 8; nt++) {
                    float e0 = __expf(p[mt][nt][r2 * 2 + 0] - mx);
                    float e1 = __expf(p[mt][nt][r2 * 2 + 1] - mx);
                    p[mt][nt][r2 * 2 + 0] = e0;
                    p[mt][nt][r2 * 2 + 1] = e1;
                    sum += e0 + e1;
                }
                sum += __shfl_xor_sync(0xffffffffu, sum, 1);
                sum += __shfl_xor_sync(0xffffffffu, sum, 2);
                float rs = 1.0f / sum;
                #pragma unroll
                for (int nt = 0; nt < 8; nt++) {
                    p[mt][nt][r2 * 2 + 0] *= rs;
                    p[mt][nt][r2 * 2 + 1] *= rs;
                }
            }
        }

        // ---- PV ----
        float o[2][4][4];
        #pragma unroll
        for (int mt = 0; mt < 2; mt++)
            #pragma unroll
            for (int nt = 0; nt < 4; nt++)
                #pragma unroll
                for (int e = 0; e < 4; e++) o[mt][nt][e] = 0.0f;

        const int s0 = g * 4 + (qd >> 1);
        const int s1 = s0 + 2;
        const bool odd = (qd & 1);

        #pragma unroll
        for (int kt = 0; kt < 8; kt++) {
            uint32_t phi[2][4], plo[2][4];
            #pragma unroll
            for (int mt = 0; mt < 2; mt++) {
                float e0 = __shfl_sync(0xffffffffu, p[mt][kt][0], s0);
                float e1 = __shfl_sync(0xffffffffu, p[mt][kt][1], s0);
                float e2 = __shfl_sync(0xffffffffu, p[mt][kt][2], s0);
                float e3 = __shfl_sync(0xffffffffu, p[mt][kt][3], s0);
                float f0 = __shfl_sync(0xffffffffu, p[mt][kt][0], s1);
                float f1 = __shfl_sync(0xffffffffu, p[mt][kt][1], s1);
                float f2 = __shfl_sync(0xffffffffu, p[mt][kt][2], s1);
                float f3 = __shfl_sync(0xffffffffu, p[mt][kt][3], s1);
                tfsplit(odd ? e1 : e0, phi[mt][0], plo[mt][0]);
                tfsplit(odd ? e3 : e2, phi[mt][1], plo[mt][1]);
                tfsplit(odd ? f1 : f0, phi[mt][2], plo[mt][2]);
                tfsplit(odd ? f3 : f2, phi[mt][3], plo[mt][3]);
            }
            #pragma unroll
            for (int nt = 0; nt < 4; nt++) {
                int cv = (nt * 8 + g) ^ (qd << 3);
                float v0 = sv[(h * 64 + kt * 8 + qd) * 32 + cv];
                float v1 = sv[(h * 64 + kt * 8 + qd + 4) * 32 + cv];
                uint32_t vh0, vl0, vh1, vl1;
                tfsplit(v0, vh0, vl0);
                tfsplit(v1, vh1, vl1);
                #pragma unroll
                for (int mt = 0; mt < 2; mt++) {
                    mma8(o[mt][nt], phi[mt], vh0, vh1);
                    mma8(o[mt][nt], phi[mt], vl0, vl1);
                    mma8(o[mt][nt], plo[mt], vh0, vh1);
                }
            }
        }

        // ---- write attn output as hi + packed lo (swizzled) ----
        #pragma unroll
        for (int mt = 0; mt < 2; mt++) {
            #pragma unroll
            for (int nt = 0; nt < 4; nt++) {
                int col0 = h * 32 + nt * 8 + qd * 2;
                #pragma unroll
                for (int r2 = 0; r2 < 2; r2++) {
                    int row = m0 + mt * 16 + g + 8 * r2;
                    float o0 = o[mt][nt][r2 * 2 + 0];
                    float o1 = o[mt][nt][r2 * 2 + 1];
                    float h0 = f2tff(o0), h1 = f2tff(o1);
                    *(float2*)&sxh[row * SXS + (col0 ^ swg)] = make_float2(h0, h1);
                    sal[row * SLS + ((col0 >> 1) ^ swg)] = packbf(o1 - h1, o0 - h0);
                }
            }
        }
    }
    __syncthreads();

    // ============ Phase 3: proj GEMM (tf32-hi + bf16-corr) ============
    {
        const int mg = w & 1;
        const int ng = w >> 1;

        float acc[2][4][4];
        #pragma unroll
        for (int a = 0; a < 2; a++)
            #pragma unroll
            for (int nt = 0; nt < 4; nt++)
                #pragma unroll
                for (int e = 0; e < 4; e++) acc[a][nt][e] = 0.0f;

        const uint4* wtab = &g_wp[(ng * 24 * 4) * 32 + lane];

        for (int ks = 0; ks < 24; ks++) {
            int k0 = ks * 8;
            uint32_t ah[2][4], ac[2][4];
            #pragma unroll
            for (int mt = 0; mt < 2; mt++) {
                int r0 = mg * 32 + mt * 16 + g;
                const float* X0 = &sxh[r0 * SXS];
                const float* X8 = X0 + 8 * SXS;
                int cA = (k0 + qd) ^ swg, cB = (k0 + qd + 4) ^ swg;
                ah[mt][0] = __float_as_uint(X0[cA]);
                ah[mt][1] = __float_as_uint(X8[cA]);
                ah[mt][2] = __float_as_uint(X0[cB]);
                ah[mt][3] = __float_as_uint(X8[cB]);
                int cC = (k0 + 2 * qd) ^ swg;
                float2 p0 = *(const float2*)&X0[cC];
                float2 p8 = *(const float2*)&X8[cC];
                ac[mt][0] = packbf(p0.y, p0.x);
                ac[mt][1] = packbf(p8.y, p8.x);
                int cU = ((k0 >> 1) + qd) ^ swg;
                ac[mt][2] = sal[r0 * SLS + cU];
                ac[mt][3] = sal[(r0 + 8) * SLS + cU];
            }
            const uint4* wrow = wtab + (ks * 4) * 32;
            #pragma unroll
            for (int nt = 0; nt < 4; nt++) {
                uint4 bb = wrow[nt * 32];
                #pragma unroll
                for (int mt = 0; mt < 2; mt++) {
                    mma8(acc[mt][nt], ah[mt], bb.x, bb.y);
                    mma16bf(acc[mt][nt], ac[mt], bb.z, bb.w);
                }
            }
        }

        float* ob = out + (size_t)b * NSEQ * CDIM;
        #pragma unroll
        for (int mt = 0; mt < 2; mt++) {
            #pragma unroll
            for (int nt = 0; nt < 4; nt++) {
                int col0 = ng * 32 + nt * 8 + qd * 2;
                float pb0 = proj_b[col0], pb1 = proj_b[col0 + 1];
                #pragma unroll
                for (int rr = 0; rr < 2; rr++) {
                    int n = mg * 32 + mt * 16 + g + rr * 8;
                    *(float2*)&ob[n * 192 + col0] =
                        make_float2(acc[mt][nt][rr * 2 + 0] + pb0,
                                    acc[mt][nt][rr * 2 + 1] + pb1);
                }
            }
        }
    }
}

// ---------------------------------------------------------------------------
extern "C" void kernel_launch(void* const* d_in, const int* in_sizes, int n_in,
                              void* d_out, int out_size)
{
    const float* x           = (const float*)d_in[0];
    const float* mask        = (const float*)d_in[1];
    const float* qkv_w       = (const float*)d_in[2];
    const float* q_bias      = (const float*)d_in[3];
    const float* v_bias      = (const float*)d_in[4];
    const float* logit_scale = (const float*)d_in[5];
    const float* cpb_w1      = (const float*)d_in[6];
    const float* cpb_b1      = (const float*)d_in[7];
    const float* cpb_w2      = (const float*)d_in[8];
    const float* proj_w      = (const float*)d_in[9];
    const float* proj_b      = (const float*)d_in[10];
    float* out = (float*)d_out;

    cudaFuncSetAttribute(win_attn_kernel,
                         cudaFuncAttributeMaxDynamicSharedMemorySize, SMEM_BYTES);

    prep_w_kernel<<<(QKV_TBL + PRJ_TBL + 255) / 256, 256>>>(qkv_w, proj_w);
    cpb_kernel<<<1, 256>>>(cpb_w1, cpb_b1, cpb_w2);
    bm_kernel<<<NW * NH, 256>>>(mask);
    win_attn_kernel<<<B_TOT, NTHREADS, SMEM_BYTES>>>(
        x, q_bias, v_bias, logit_scale, proj_b, out);
}